// round 5
// baseline (speedup 1.0000x reference)
#include <cuda_runtime.h>
#include <cuda_bf16.h>
#include <cstdint>

#define NROWS 16384
#define DIM   1024
#define NCENT 1024
#define MARGIN 0.35f

#define BM 128
#define BN 128
#define BK 32
#define PAD_K 40   // bf16 elems per smem row (80B stride -> conflict-free ldmatrix)
#define NITER (DIM / BK)

// ---- scratch (device globals only; no runtime allocation allowed) ----
__device__ float         g_xsq[NROWS];
__device__ float         g_csq[NCENT];
__device__ unsigned      g_rowmin[NROWS];               // ordered-key min of s
__device__ __nv_bfloat16 g_xb[(size_t)NROWS * DIM];     // 32 MB
__device__ __nv_bfloat16 g_cb[(size_t)NCENT * DIM];     //  2 MB
__device__ __nv_bfloat16 g_sc[(size_t)NROWS * NCENT];   // 32 MB  s = -2dot+csq

// ---- ordered-float <-> uint key (monotone, handles negatives) ----
__device__ __forceinline__ unsigned fenc(float f) {
    unsigned u = __float_as_uint(f);
    return (u & 0x80000000u) ? ~u : (u | 0x80000000u);
}
__device__ __forceinline__ float fdec(unsigned k) {
    return (k & 0x80000000u) ? __uint_as_float(k & 0x7FFFFFFFu)
                             : __uint_as_float(~k);
}

// ---------------------------------------------------------------------------
// Prep: exact fp32 sum-of-squares + bf16 conversion + rowmin init.
// ---------------------------------------------------------------------------
__global__ __launch_bounds__(256) void prep_x_kernel(const float* __restrict__ x) {
    __shared__ float s[256];
    const int r = blockIdx.x, t = threadIdx.x;
    const float4 v = ((const float4*)(x + (size_t)r * DIM))[t];
    __nv_bfloat162 b01, b23;
    b01.x = __float2bfloat16(v.x); b01.y = __float2bfloat16(v.y);
    b23.x = __float2bfloat16(v.z); b23.y = __float2bfloat16(v.w);
    __nv_bfloat162* dst = (__nv_bfloat162*)(g_xb + (size_t)r * DIM);
    dst[t * 2 + 0] = b01;
    dst[t * 2 + 1] = b23;
    float acc = fmaf(v.x, v.x, 0.f);
    acc = fmaf(v.y, v.y, acc);
    acc = fmaf(v.z, v.z, acc);
    acc = fmaf(v.w, v.w, acc);
    s[t] = acc;
    __syncthreads();
    #pragma unroll
    for (int off = 128; off > 0; off >>= 1) {
        if (t < off) s[t] += s[t + off];
        __syncthreads();
    }
    if (t == 0) {
        g_xsq[r] = s[0];
        g_rowmin[r] = 0xFFFFFFFFu;
    }
}

__global__ __launch_bounds__(256) void prep_c_kernel(const float* __restrict__ c) {
    __shared__ float s[256];
    const int r = blockIdx.x, t = threadIdx.x;
    const float4 v = ((const float4*)(c + (size_t)r * DIM))[t];
    __nv_bfloat162 b01, b23;
    b01.x = __float2bfloat16(v.x); b01.y = __float2bfloat16(v.y);
    b23.x = __float2bfloat16(v.z); b23.y = __float2bfloat16(v.w);
    __nv_bfloat162* dst = (__nv_bfloat162*)(g_cb + (size_t)r * DIM);
    dst[t * 2 + 0] = b01;
    dst[t * 2 + 1] = b23;
    float acc = fmaf(v.x, v.x, 0.f);
    acc = fmaf(v.y, v.y, acc);
    acc = fmaf(v.z, v.z, acc);
    acc = fmaf(v.w, v.w, acc);
    s[t] = acc;
    __syncthreads();
    #pragma unroll
    for (int off = 128; off > 0; off >>= 1) {
        if (t < off) s[t] += s[t + off];
        __syncthreads();
    }
    if (t == 0) g_csq[r] = s[0];
}

// ---------------------------------------------------------------------------
// Stage 1: bf16 HMMA GEMM (mma.sync m16n8k16), 128x128x32 tiles, 8 warps.
// True double-buffered cp.async (one group in flight). Scores -> bf16.
// ---------------------------------------------------------------------------
__device__ __forceinline__ void cp16(uint32_t dst, const void* src) {
    asm volatile("cp.async.cg.shared.global [%0], [%1], 16;\n" :: "r"(dst), "l"(src));
}
__device__ __forceinline__ void ldsm4(uint32_t* r, uint32_t addr) {
    asm volatile("ldmatrix.sync.aligned.m8n8.x4.shared.b16 {%0,%1,%2,%3}, [%4];"
                 : "=r"(r[0]), "=r"(r[1]), "=r"(r[2]), "=r"(r[3]) : "r"(addr));
}
__device__ __forceinline__ void mma16816(float* c, const uint32_t* a, uint32_t b0, uint32_t b1) {
    asm volatile("mma.sync.aligned.m16n8k16.row.col.f32.bf16.bf16.f32 "
                 "{%0,%1,%2,%3}, {%4,%5,%6,%7}, {%8,%9}, {%0,%1,%2,%3};"
                 : "+f"(c[0]), "+f"(c[1]), "+f"(c[2]), "+f"(c[3])
                 : "r"(a[0]), "r"(a[1]), "r"(a[2]), "r"(a[3]), "r"(b0), "r"(b1));
}

__global__ __launch_bounds__(256, 2) void mma_score_kernel() {
    __shared__ __align__(128) __nv_bfloat16 As[2][BM * PAD_K];
    __shared__ __align__(128) __nv_bfloat16 Bs[2][BN * PAD_K];
    __shared__ float s_csq[BN];

    const int tid  = threadIdx.x;
    const int warp = tid >> 5, lane = tid & 31;
    const int wm = warp >> 1, wn = warp & 1;
    const int m0 = blockIdx.y * BM;
    const int n0 = blockIdx.x * BN;

    float acc[2][8][4];
    #pragma unroll
    for (int i = 0; i < 2; i++)
        #pragma unroll
        for (int j = 0; j < 8; j++)
            #pragma unroll
            for (int k = 0; k < 4; k++) acc[i][j][k] = 0.f;

    uint32_t sA[2], sB[2];
    sA[0] = (uint32_t)__cvta_generic_to_shared(&As[0][0]);
    sA[1] = (uint32_t)__cvta_generic_to_shared(&As[1][0]);
    sB[0] = (uint32_t)__cvta_generic_to_shared(&Bs[0][0]);
    sB[1] = (uint32_t)__cvta_generic_to_shared(&Bs[1][0]);

    if (tid < BN / 2)
        *(float2*)&s_csq[tid * 2] = *(const float2*)&g_csq[n0 + tid * 2];

    // tile loaders: thread -> row tid>>1, 32B half (tid&1)
    const int lr = tid >> 1;
    const int lc = (tid & 1) * 16;
    const uint32_t dOff = (uint32_t)(lr * PAD_K + lc) * 2;

    auto load_tile = [&](int buf, int k0) {
        const __nv_bfloat16* srcA = g_xb + (size_t)(m0 + lr) * DIM + k0 + lc;
        cp16(sA[buf] + dOff,      srcA);
        cp16(sA[buf] + dOff + 16, srcA + 8);
        const __nv_bfloat16* srcB = g_cb + (size_t)(n0 + lr) * DIM + k0 + lc;
        cp16(sB[buf] + dOff,      srcB);
        cp16(sB[buf] + dOff + 16, srcB + 8);
        asm volatile("cp.async.commit_group;");
    };

    load_tile(0, 0);
    load_tile(1, BK);

    // ldmatrix lane geometry
    const int a_row = (lane & 7) + ((lane >> 3) & 1) * 8;
    const int a_kof = (lane >> 4) * 8;
    const int b_row = (lane & 7) + (lane >> 4) * 8;
    const int b_kof = ((lane >> 3) & 1) * 8;

    #pragma unroll 1
    for (int kt = 0; kt < NITER; kt++) {
        const int buf = kt & 1;
        if (kt == NITER - 1) asm volatile("cp.async.wait_group 0;");
        else                 asm volatile("cp.async.wait_group 1;");
        __syncthreads();

        #pragma unroll
        for (int ks = 0; ks < BK; ks += 16) {
            uint32_t af[2][4];
            #pragma unroll
            for (int mi = 0; mi < 2; mi++) {
                uint32_t addr = sA[buf] +
                    (uint32_t)((wm * 32 + mi * 16 + a_row) * PAD_K + ks + a_kof) * 2;
                ldsm4(af[mi], addr);
            }
            #pragma unroll
            for (int nt = 0; nt < 4; nt++) {
                uint32_t bf[4];
                uint32_t addr = sB[buf] +
                    (uint32_t)((wn * 64 + nt * 16 + b_row) * PAD_K + ks + b_kof) * 2;
                ldsm4(bf, addr);
                #pragma unroll
                for (int mi = 0; mi < 2; mi++) {
                    mma16816(acc[mi][2 * nt + 0], af[mi], bf[0], bf[1]);
                    mma16816(acc[mi][2 * nt + 1], af[mi], bf[2], bf[3]);
                }
            }
        }

        __syncthreads();
        if (kt + 2 < NITER) load_tile(buf, (kt + 2) * BK);
    }

    // epilogue: s = fmaf(-2, dot, csq), bf16 store, per-row ordered min
    #pragma unroll
    for (int mi = 0; mi < 2; mi++) {
        #pragma unroll
        for (int h = 0; h < 2; h++) {
            const int gr = m0 + wm * 32 + mi * 16 + h * 8 + (lane >> 2);
            float lmin = 3.4e38f;
            __nv_bfloat16* srow = g_sc + (size_t)gr * NCENT + n0;
            #pragma unroll
            for (int ni = 0; ni < 8; ni++) {
                const int lc2 = wn * 64 + ni * 8 + (lane & 3) * 2;
                const float s0 = fmaf(-2.f, acc[mi][ni][h * 2 + 0], s_csq[lc2 + 0]);
                const float s1 = fmaf(-2.f, acc[mi][ni][h * 2 + 1], s_csq[lc2 + 1]);
                lmin = fminf(lmin, fminf(s0, s1));
                __nv_bfloat162 p;
                p.x = __float2bfloat16(s0);
                p.y = __float2bfloat16(s1);
                *(__nv_bfloat162*)(srow + lc2) = p;
            }
            lmin = fminf(lmin, __shfl_xor_sync(0xffffffffu, lmin, 1));
            lmin = fminf(lmin, __shfl_xor_sync(0xffffffffu, lmin, 2));
            if ((lane & 3) == 0)
                atomicMin(&g_rowmin[gr], fenc(lmin));
        }
    }
}

// ---------------------------------------------------------------------------
// Stage 2 (fused): candidate scan -> (fast path | exact fp32 rescore) ->
// gather table row + bias into output. One block per row.
// ---------------------------------------------------------------------------
__global__ __launch_bounds__(256) void rescore_gather_kernel(
    const float* __restrict__ x, const float* __restrict__ cent,
    const float* __restrict__ table, const float* __restrict__ bias,
    float* __restrict__ out)
{
    __shared__ int   s_cand[256];
    __shared__ int   s_cnt;
    __shared__ int   s_idx;
    __shared__ float s_red[8];

    const int r = blockIdx.x, t = threadIdx.x;
    if (t == 0) s_cnt = 0;
    __syncthreads();

    const float thr = fdec(g_rowmin[r]) + MARGIN;
    const __nv_bfloat162* srow = (const __nv_bfloat162*)(g_sc + (size_t)r * NCENT);
    {
        const __nv_bfloat162 p0 = srow[t * 2 + 0];
        const __nv_bfloat162 p1 = srow[t * 2 + 1];
        const float v[4] = { __bfloat162float(p0.x), __bfloat162float(p0.y),
                             __bfloat162float(p1.x), __bfloat162float(p1.y) };
        #pragma unroll
        for (int j = 0; j < 4; j++) {
            if (v[j] <= thr) {
                int p = atomicAdd(&s_cnt, 1);
                if (p < 256) s_cand[p] = t * 4 + j;
            }
        }
    }
    __syncthreads();
    const int cnt = min(s_cnt, 256);

    if (cnt == 1) {
        if (t == 0) s_idx = s_cand[0];
    } else {
        const float* xr = x + (size_t)r * DIM;
        const float x0 = xr[t], x1 = xr[t + 256], x2 = xr[t + 512], x3 = xr[t + 768];
        const float xs = g_xsq[r];

        float best = 3.4e38f;
        int bidx = NCENT;
        for (int ci = 0; ci < cnt; ci++) {
            const int c = s_cand[ci];
            const float* cr = cent + (size_t)c * DIM;
            float a = fmaf(x0, cr[t], 0.f);
            a = fmaf(x1, cr[t + 256], a);
            a = fmaf(x2, cr[t + 512], a);
            a = fmaf(x3, cr[t + 768], a);
            #pragma unroll
            for (int o = 16; o > 0; o >>= 1)
                a += __shfl_xor_sync(0xffffffffu, a, o);
            if ((t & 31) == 0) s_red[t >> 5] = a;
            __syncthreads();
            if (t == 0) {
                float dot = s_red[0];
                #pragma unroll
                for (int w = 1; w < 8; w++) dot += s_red[w];
                const float d = fmaf(-2.f, dot, xs) + g_csq[c];
                if (d < best || (d == best && c < bidx)) { best = d; bidx = c; }
            }
            __syncthreads();
        }
        if (t == 0) s_idx = bidx;
    }
    __syncthreads();

    // gather: out[r] = table[idx] + bias
    const int idx = s_idx;
    const float4 a = ((const float4*)(table + (size_t)idx * DIM))[t];
    const float4 b = ((const float4*)bias)[t];
    ((float4*)(out + (size_t)r * DIM))[t] =
        make_float4(a.x + b.x, a.y + b.y, a.z + b.z, a.w + b.w);
}

// ---------------------------------------------------------------------------
extern "C" void kernel_launch(void* const* d_in, const int* in_sizes, int n_in,
                              void* d_out, int out_size) {
    const float* x     = (const float*)d_in[0];  // [4,4096,1024]
    const float* cent  = (const float*)d_in[1];  // [1024,1024]
    const float* table = (const float*)d_in[2];  // [1024,1024]
    const float* bias  = (const float*)d_in[3];  // [1024]
    float* out = (float*)d_out;

    prep_x_kernel<<<NROWS, 256>>>(x);
    prep_c_kernel<<<NCENT, 256>>>(cent);
    mma_score_kernel<<<dim3(NCENT / BN, NROWS / BM), 256>>>();
    rescore_gather_kernel<<<NROWS, 256>>>(x, cent, table, bias, out);
}

// round 6
// speedup vs baseline: 1.3951x; 1.3951x over previous
#include <cuda_runtime.h>
#include <cuda_bf16.h>
#include <cstdint>

#define NROWS 16384
#define DIM   1024
#define NCENT 1024
#define MARGIN 0.35f

#define BM 128
#define BN 128
#define BK 64
#define PAD_K 72   // bf16 elems per smem row (144B stride -> conflict-free ldmatrix)
#define NITER (DIM / BK)

// ---- scratch (device globals only; no runtime allocation allowed) ----
__device__ float         g_xsq[NROWS];
__device__ float         g_csq[NCENT];
__device__ unsigned      g_rowmin[NROWS];
__device__ int           g_idx[NROWS];
__device__ __nv_bfloat16 g_xb[(size_t)NROWS * DIM];      // 32 MB
__device__ __nv_bfloat16 g_cb[(size_t)NCENT * DIM];      //  2 MB
__device__ float         g_scores[(size_t)NROWS * NCENT];// 64 MB

// ---------------------------------------------------------------------------
// Prep: exact fp32 sum-of-squares + bf16 conversion + rowmin init.
// ---------------------------------------------------------------------------
__global__ __launch_bounds__(256) void prep_x_kernel(const float* __restrict__ x) {
    __shared__ float s[256];
    const int r = blockIdx.x, t = threadIdx.x;
    const float4 v = ((const float4*)(x + (size_t)r * DIM))[t];
    __nv_bfloat162 b01, b23;
    b01.x = __float2bfloat16(v.x); b01.y = __float2bfloat16(v.y);
    b23.x = __float2bfloat16(v.z); b23.y = __float2bfloat16(v.w);
    __nv_bfloat162* dst = (__nv_bfloat162*)(g_xb + (size_t)r * DIM);
    dst[t * 2 + 0] = b01;
    dst[t * 2 + 1] = b23;
    float acc = fmaf(v.x, v.x, 0.f);
    acc = fmaf(v.y, v.y, acc);
    acc = fmaf(v.z, v.z, acc);
    acc = fmaf(v.w, v.w, acc);
    s[t] = acc;
    __syncthreads();
    #pragma unroll
    for (int off = 128; off > 0; off >>= 1) {
        if (t < off) s[t] += s[t + off];
        __syncthreads();
    }
    if (t == 0) {
        g_xsq[r] = s[0];
        g_rowmin[r] = 0x7F7FFFFFu;  // FLT_MAX bits (scores d2 > 0 always)
    }
}

__global__ __launch_bounds__(256) void prep_c_kernel(const float* __restrict__ c) {
    __shared__ float s[256];
    const int r = blockIdx.x, t = threadIdx.x;
    const float4 v = ((const float4*)(c + (size_t)r * DIM))[t];
    __nv_bfloat162 b01, b23;
    b01.x = __float2bfloat16(v.x); b01.y = __float2bfloat16(v.y);
    b23.x = __float2bfloat16(v.z); b23.y = __float2bfloat16(v.w);
    __nv_bfloat162* dst = (__nv_bfloat162*)(g_cb + (size_t)r * DIM);
    dst[t * 2 + 0] = b01;
    dst[t * 2 + 1] = b23;
    float acc = fmaf(v.x, v.x, 0.f);
    acc = fmaf(v.y, v.y, acc);
    acc = fmaf(v.z, v.z, acc);
    acc = fmaf(v.w, v.w, acc);
    s[t] = acc;
    __syncthreads();
    #pragma unroll
    for (int off = 128; off > 0; off >>= 1) {
        if (t < off) s[t] += s[t + off];
        __syncthreads();
    }
    if (t == 0) g_csq[r] = s[0];
}

// ---------------------------------------------------------------------------
// Stage 1: bf16 HMMA GEMM (mma.sync m16n8k16), 128x128x64 tiles, 8 warps.
// R2 pipeline shape (prefetch at top, wait after MMA), BK doubled to 64.
// Scores d2 stored fp32, coalesced float2; per-row min via atomicMin on bits.
// ---------------------------------------------------------------------------
__device__ __forceinline__ void cp16(uint32_t dst, const void* src) {
    asm volatile("cp.async.cg.shared.global [%0], [%1], 16;\n" :: "r"(dst), "l"(src));
}
__device__ __forceinline__ void ldsm4(uint32_t* r, uint32_t addr) {
    asm volatile("ldmatrix.sync.aligned.m8n8.x4.shared.b16 {%0,%1,%2,%3}, [%4];"
                 : "=r"(r[0]), "=r"(r[1]), "=r"(r[2]), "=r"(r[3]) : "r"(addr));
}
__device__ __forceinline__ void mma16816(float* c, const uint32_t* a, uint32_t b0, uint32_t b1) {
    asm volatile("mma.sync.aligned.m16n8k16.row.col.f32.bf16.bf16.f32 "
                 "{%0,%1,%2,%3}, {%4,%5,%6,%7}, {%8,%9}, {%0,%1,%2,%3};"
                 : "+f"(c[0]), "+f"(c[1]), "+f"(c[2]), "+f"(c[3])
                 : "r"(a[0]), "r"(a[1]), "r"(a[2]), "r"(a[3]), "r"(b0), "r"(b1));
}

#define TILE_BYTES (BM * PAD_K * 2)          // 18432 B per tile per buffer

__global__ __launch_bounds__(256, 2) void mma_score_kernel() {
    extern __shared__ __align__(128) char dsm[];

    const int tid  = threadIdx.x;
    const int warp = tid >> 5, lane = tid & 31;
    const int wm = warp >> 1, wn = warp & 1;
    const int m0 = blockIdx.y * BM;
    const int n0 = blockIdx.x * BN;

    float acc[2][8][4];
    #pragma unroll
    for (int i = 0; i < 2; i++)
        #pragma unroll
        for (int j = 0; j < 8; j++)
            #pragma unroll
            for (int k = 0; k < 4; k++) acc[i][j][k] = 0.f;

    const uint32_t sbase = (uint32_t)__cvta_generic_to_shared(dsm);
    uint32_t sA[2], sB[2];
    sA[0] = sbase;
    sA[1] = sbase + TILE_BYTES;
    sB[0] = sbase + 2 * TILE_BYTES;
    sB[1] = sbase + 3 * TILE_BYTES;

    // tile loaders: thread -> row tid>>1, 64B half (tid&1), 4x cp16 per matrix
    const int lr = tid >> 1;
    const int lc = (tid & 1) * 32;                 // bf16 elems
    const uint32_t dOff = (uint32_t)(lr * PAD_K + lc) * 2;

    auto load_tile = [&](int buf, int k0) {
        const __nv_bfloat16* srcA = g_xb + (size_t)(m0 + lr) * DIM + k0 + lc;
        const __nv_bfloat16* srcB = g_cb + (size_t)(n0 + lr) * DIM + k0 + lc;
        #pragma unroll
        for (int i = 0; i < 4; i++) {
            cp16(sA[buf] + dOff + i * 16, srcA + i * 8);
            cp16(sB[buf] + dOff + i * 16, srcB + i * 8);
        }
        asm volatile("cp.async.commit_group;");
    };

    load_tile(0, 0);
    asm volatile("cp.async.wait_group 0;");
    __syncthreads();

    // ldmatrix lane geometry
    const int a_row = (lane & 7) + ((lane >> 3) & 1) * 8;
    const int a_kof = (lane >> 4) * 8;
    const int b_row = (lane & 7) + (lane >> 4) * 8;
    const int b_kof = ((lane >> 3) & 1) * 8;

    #pragma unroll 1
    for (int kt = 0; kt < NITER; kt++) {
        const int buf = kt & 1;
        if (kt + 1 < NITER) load_tile(buf ^ 1, (kt + 1) * BK);

        #pragma unroll
        for (int ks = 0; ks < BK; ks += 16) {
            uint32_t af[2][4];
            #pragma unroll
            for (int mi = 0; mi < 2; mi++) {
                uint32_t addr = sA[buf] +
                    (uint32_t)((wm * 32 + mi * 16 + a_row) * PAD_K + ks + a_kof) * 2;
                ldsm4(af[mi], addr);
            }
            #pragma unroll
            for (int nt = 0; nt < 4; nt++) {
                uint32_t bf[4];
                uint32_t addr = sB[buf] +
                    (uint32_t)((wn * 64 + nt * 16 + b_row) * PAD_K + ks + b_kof) * 2;
                ldsm4(bf, addr);
                #pragma unroll
                for (int mi = 0; mi < 2; mi++) {
                    mma16816(acc[mi][2 * nt + 0], af[mi], bf[0], bf[1]);
                    mma16816(acc[mi][2 * nt + 1], af[mi], bf[2], bf[3]);
                }
            }
        }

        asm volatile("cp.async.wait_group 0;");
        __syncthreads();
    }

    // epilogue: d2 = fmaf(-2, dot, xsq) + csq ; fp32 coalesced stores + rowmin
    #pragma unroll
    for (int mi = 0; mi < 2; mi++) {
        #pragma unroll
        for (int h = 0; h < 2; h++) {
            const int gr = m0 + wm * 32 + mi * 16 + h * 8 + (lane >> 2);
            const float xs = g_xsq[gr];
            float lmin = 3.4e38f;
            float* srow = g_scores + (size_t)gr * NCENT;
            #pragma unroll
            for (int ni = 0; ni < 8; ni++) {
                const int gc = n0 + wn * 64 + ni * 8 + (lane & 3) * 2;
                const float v0 = fmaf(-2.f, acc[mi][ni][h * 2 + 0], xs) + g_csq[gc];
                const float v1 = fmaf(-2.f, acc[mi][ni][h * 2 + 1], xs) + g_csq[gc + 1];
                *(float2*)(srow + gc) = make_float2(v0, v1);
                lmin = fminf(lmin, fminf(v0, v1));
            }
            lmin = fminf(lmin, __shfl_xor_sync(0xffffffffu, lmin, 1));
            lmin = fminf(lmin, __shfl_xor_sync(0xffffffffu, lmin, 2));
            if ((lane & 3) == 0)
                atomicMin(&g_rowmin[gr], __float_as_uint(lmin));  // d2 > 0
        }
    }
}

// ---------------------------------------------------------------------------
// Stage 2: candidate scan; cnt==1 fast path (provably exact), else exact fp32
// rescore with the reference-faithful formula fmaf(-2,dot,xsq)+csq.
// ---------------------------------------------------------------------------
__global__ __launch_bounds__(256) void rescore_kernel(
    const float* __restrict__ x, const float* __restrict__ cent)
{
    __shared__ int   s_cand[NCENT];
    __shared__ int   s_cnt;
    __shared__ float s_red[8];

    const int r = blockIdx.x, t = threadIdx.x;
    if (t == 0) s_cnt = 0;
    __syncthreads();

    const float thr = __uint_as_float(g_rowmin[r]) + MARGIN;
    const float* srow = g_scores + (size_t)r * NCENT;
    #pragma unroll
    for (int j = t; j < NCENT; j += 256) {
        if (srow[j] <= thr) {
            int p = atomicAdd(&s_cnt, 1);
            s_cand[p] = j;
        }
    }
    __syncthreads();
    const int cnt = s_cnt;

    if (cnt == 1) {               // unique candidate within margin: exact winner
        if (t == 0) g_idx[r] = s_cand[0];
        return;
    }

    const float* xr = x + (size_t)r * DIM;
    const float x0 = xr[t], x1 = xr[t + 256], x2 = xr[t + 512], x3 = xr[t + 768];
    const float xs = g_xsq[r];

    float best = 3.4e38f;
    int bidx = NCENT;
    for (int ci = 0; ci < cnt; ci++) {
        const int c = s_cand[ci];
        const float* cr = cent + (size_t)c * DIM;
        float a = fmaf(x0, cr[t], 0.f);
        a = fmaf(x1, cr[t + 256], a);
        a = fmaf(x2, cr[t + 512], a);
        a = fmaf(x3, cr[t + 768], a);
        #pragma unroll
        for (int o = 16; o > 0; o >>= 1)
            a += __shfl_xor_sync(0xffffffffu, a, o);
        if ((t & 31) == 0) s_red[t >> 5] = a;
        __syncthreads();
        if (t == 0) {
            float dot = s_red[0];
            #pragma unroll
            for (int w = 1; w < 8; w++) dot += s_red[w];
            const float d = fmaf(-2.f, dot, xs) + g_csq[c];
            if (d < best || (d == best && c < bidx)) { best = d; bidx = c; }
        }
        __syncthreads();
    }
    if (t == 0) g_idx[r] = bidx;
}

// ---------------------------------------------------------------------------
// Gather: out[r] = table[idx[r]] + bias (table L2-resident; write-bound).
// ---------------------------------------------------------------------------
__global__ __launch_bounds__(256) void gather_kernel(
    const float* __restrict__ table, const float* __restrict__ bias,
    float* __restrict__ out)
{
    const int r = blockIdx.x;
    const int idx = g_idx[r];
    const float4* src = (const float4*)(table + (size_t)idx * DIM);
    const float4* bv  = (const float4*)bias;
    float4* dst = (float4*)(out + (size_t)r * DIM);
    float4 a = src[threadIdx.x];
    float4 b = bv[threadIdx.x];
    dst[threadIdx.x] = make_float4(a.x + b.x, a.y + b.y, a.z + b.z, a.w + b.w);
}

// ---------------------------------------------------------------------------
extern "C" void kernel_launch(void* const* d_in, const int* in_sizes, int n_in,
                              void* d_out, int out_size) {
    const float* x     = (const float*)d_in[0];  // [4,4096,1024]
    const float* cent  = (const float*)d_in[1];  // [1024,1024]
    const float* table = (const float*)d_in[2];  // [1024,1024]
    const float* bias  = (const float*)d_in[3];  // [1024]
    float* out = (float*)d_out;

    const int dsm_bytes = 4 * TILE_BYTES;       // 73728 B (2 bufs x (A+B))
    cudaFuncSetAttribute(mma_score_kernel,
                         cudaFuncAttributeMaxDynamicSharedMemorySize, dsm_bytes);

    prep_x_kernel<<<NROWS, 256>>>(x);
    prep_c_kernel<<<NCENT, 256>>>(cent);
    mma_score_kernel<<<dim3(NCENT / BN, NROWS / BM), 256, dsm_bytes>>>();
    rescore_kernel<<<NROWS, 256>>>(x, cent);
    gather_kernel<<<NROWS, 256>>>(table, bias, out);
}

// round 8
// speedup vs baseline: 1.4834x; 1.0633x over previous
#include <cuda_runtime.h>
#include <cuda_bf16.h>
#include <cstdint>

#define NROWS 16384
#define DIM   1024
#define NCENT 1024
#define MARGIN 0.35f

#define BM 128
#define BN 128
#define BK 32
#define PAD_K 40   // bf16 elems per smem row (80B stride -> conflict-free ldmatrix)
#define NITER (DIM / BK)
#define SROW 136   // score-stage smem row stride (bf16): 272B, 16B-aligned rows

// ---- scratch (device globals only; no runtime allocation allowed) ----
__device__ float         g_xsq[NROWS];
__device__ float         g_csq[NCENT];
__device__ unsigned      g_rowmin[NROWS];               // ordered-key min of s
__device__ int           g_idx[NROWS];
__device__ __nv_bfloat16 g_xb[(size_t)NROWS * DIM];     // 32 MB
__device__ __nv_bfloat16 g_cb[(size_t)NCENT * DIM];     //  2 MB
__device__ __nv_bfloat16 g_sc[(size_t)NROWS * NCENT];   // 32 MB  s = -2dot+csq

// ---- ordered-float <-> uint key (monotone, handles negatives) ----
__device__ __forceinline__ unsigned fenc(float f) {
    unsigned u = __float_as_uint(f);
    return (u & 0x80000000u) ? ~u : (u | 0x80000000u);
}
__device__ __forceinline__ float fdec(unsigned k) {
    return (k & 0x80000000u) ? __uint_as_float(k & 0x7FFFFFFFu)
                             : __uint_as_float(~k);
}

// ---------------------------------------------------------------------------
// Prep: exact fp32 sum-of-squares + bf16 conversion + rowmin init.
// ---------------------------------------------------------------------------
__global__ __launch_bounds__(256) void prep_x_kernel(const float* __restrict__ x) {
    __shared__ float s[256];
    const int r = blockIdx.x, t = threadIdx.x;
    const float4 v = ((const float4*)(x + (size_t)r * DIM))[t];
    __nv_bfloat162 b01, b23;
    b01.x = __float2bfloat16(v.x); b01.y = __float2bfloat16(v.y);
    b23.x = __float2bfloat16(v.z); b23.y = __float2bfloat16(v.w);
    __nv_bfloat162* dst = (__nv_bfloat162*)(g_xb + (size_t)r * DIM);
    dst[t * 2 + 0] = b01;
    dst[t * 2 + 1] = b23;
    float acc = fmaf(v.x, v.x, 0.f);
    acc = fmaf(v.y, v.y, acc);
    acc = fmaf(v.z, v.z, acc);
    acc = fmaf(v.w, v.w, acc);
    s[t] = acc;
    __syncthreads();
    #pragma unroll
    for (int off = 128; off > 0; off >>= 1) {
        if (t < off) s[t] += s[t + off];
        __syncthreads();
    }
    if (t == 0) {
        g_xsq[r] = s[0];
        g_rowmin[r] = 0xFFFFFFFFu;   // max ordered key
    }
}

__global__ __launch_bounds__(256) void prep_c_kernel(const float* __restrict__ c) {
    __shared__ float s[256];
    const int r = blockIdx.x, t = threadIdx.x;
    const float4 v = ((const float4*)(c + (size_t)r * DIM))[t];
    __nv_bfloat162 b01, b23;
    b01.x = __float2bfloat16(v.x); b01.y = __float2bfloat16(v.y);
    b23.x = __float2bfloat16(v.z); b23.y = __float2bfloat16(v.w);
    __nv_bfloat162* dst = (__nv_bfloat162*)(g_cb + (size_t)r * DIM);
    dst[t * 2 + 0] = b01;
    dst[t * 2 + 1] = b23;
    float acc = fmaf(v.x, v.x, 0.f);
    acc = fmaf(v.y, v.y, acc);
    acc = fmaf(v.z, v.z, acc);
    acc = fmaf(v.w, v.w, acc);
    s[t] = acc;
    __syncthreads();
    #pragma unroll
    for (int off = 128; off > 0; off >>= 1) {
        if (t < off) s[t] += s[t + off];
        __syncthreads();
    }
    if (t == 0) g_csq[r] = s[0];
}

// ---------------------------------------------------------------------------
// Stage 1: bf16 HMMA GEMM (R2 mainloop, measured best), 128x128x32 tiles.
// Epilogue: s = -2dot+csq -> smem stage -> coalesced bf16 writes + rowmin.
// ---------------------------------------------------------------------------
__device__ __forceinline__ void cp16(uint32_t dst, const void* src) {
    asm volatile("cp.async.cg.shared.global [%0], [%1], 16;\n" :: "r"(dst), "l"(src));
}
__device__ __forceinline__ void ldsm4(uint32_t* r, uint32_t addr) {
    asm volatile("ldmatrix.sync.aligned.m8n8.x4.shared.b16 {%0,%1,%2,%3}, [%4];"
                 : "=r"(r[0]), "=r"(r[1]), "=r"(r[2]), "=r"(r[3]) : "r"(addr));
}
__device__ __forceinline__ void mma16816(float* c, const uint32_t* a, uint32_t b0, uint32_t b1) {
    asm volatile("mma.sync.aligned.m16n8k16.row.col.f32.bf16.bf16.f32 "
                 "{%0,%1,%2,%3}, {%4,%5,%6,%7}, {%8,%9}, {%0,%1,%2,%3};"
                 : "+f"(c[0]), "+f"(c[1]), "+f"(c[2]), "+f"(c[3])
                 : "r"(a[0]), "r"(a[1]), "r"(a[2]), "r"(a[3]), "r"(b0), "r"(b1));
}

#define TILE_HALF (BM * PAD_K)                 // bf16 elems per tile buffer
#define DSM_BYTES (4 * TILE_HALF * 2)          // 40960 B (2 bufs x (A+B))

__global__ __launch_bounds__(256, 2) void mma_score_kernel() {
    extern __shared__ __align__(128) char dsm[];
    __shared__ float s_csq[BN];

    const int tid  = threadIdx.x;
    const int warp = tid >> 5, lane = tid & 31;
    const int wm = warp >> 1, wn = warp & 1;
    const int m0 = blockIdx.y * BM;
    const int n0 = blockIdx.x * BN;

    float acc[2][8][4];
    #pragma unroll
    for (int i = 0; i < 2; i++)
        #pragma unroll
        for (int j = 0; j < 8; j++)
            #pragma unroll
            for (int k = 0; k < 4; k++) acc[i][j][k] = 0.f;

    const uint32_t sbase = (uint32_t)__cvta_generic_to_shared(dsm);
    uint32_t sA[2], sB[2];
    sA[0] = sbase;
    sA[1] = sbase + TILE_HALF * 2;
    sB[0] = sbase + 2 * TILE_HALF * 2;
    sB[1] = sbase + 3 * TILE_HALF * 2;

    if (tid < BN / 2)
        *(float2*)&s_csq[tid * 2] = *(const float2*)&g_csq[n0 + tid * 2];

    // tile loaders: thread -> row tid>>1, 32B half (tid&1)
    const int lr = tid >> 1;
    const int lc = (tid & 1) * 16;
    const uint32_t dOff = (uint32_t)(lr * PAD_K + lc) * 2;

    auto load_tile = [&](int buf, int k0) {
        const __nv_bfloat16* srcA = g_xb + (size_t)(m0 + lr) * DIM + k0 + lc;
        cp16(sA[buf] + dOff,      srcA);
        cp16(sA[buf] + dOff + 16, srcA + 8);
        const __nv_bfloat16* srcB = g_cb + (size_t)(n0 + lr) * DIM + k0 + lc;
        cp16(sB[buf] + dOff,      srcB);
        cp16(sB[buf] + dOff + 16, srcB + 8);
    };

    load_tile(0, 0);
    asm volatile("cp.async.commit_group;");
    asm volatile("cp.async.wait_group 0;");
    __syncthreads();

    // ldmatrix lane geometry
    const int a_row = (lane & 7) + ((lane >> 3) & 1) * 8;
    const int a_kof = (lane >> 4) * 8;
    const int b_row = (lane & 7) + (lane >> 4) * 8;
    const int b_kof = ((lane >> 3) & 1) * 8;

    #pragma unroll 1
    for (int kt = 0; kt < NITER; kt++) {
        const int buf = kt & 1;
        if (kt + 1 < NITER) {
            load_tile(buf ^ 1, (kt + 1) * BK);
            asm volatile("cp.async.commit_group;");
        }

        #pragma unroll
        for (int ks = 0; ks < BK; ks += 16) {
            uint32_t af[2][4];
            #pragma unroll
            for (int mi = 0; mi < 2; mi++) {
                uint32_t addr = sA[buf] +
                    (uint32_t)((wm * 32 + mi * 16 + a_row) * PAD_K + ks + a_kof) * 2;
                ldsm4(af[mi], addr);
            }
            #pragma unroll
            for (int nt = 0; nt < 4; nt++) {
                uint32_t bf[4];
                uint32_t addr = sB[buf] +
                    (uint32_t)((wn * 64 + nt * 16 + b_row) * PAD_K + ks + b_kof) * 2;
                ldsm4(bf, addr);
                #pragma unroll
                for (int mi = 0; mi < 2; mi++) {
                    mma16816(acc[mi][2 * nt + 0], af[mi], bf[0], bf[1]);
                    mma16816(acc[mi][2 * nt + 1], af[mi], bf[2], bf[3]);
                }
            }
        }

        asm volatile("cp.async.wait_group 0;");
        __syncthreads();
    }

    // ---- epilogue: stage bf16 scores in smem (reuse dsm), then coalesce ----
    __nv_bfloat16* stage = (__nv_bfloat16*)dsm;   // 128 x SROW bf16 = 34816 B

    #pragma unroll
    for (int mi = 0; mi < 2; mi++) {
        #pragma unroll
        for (int h = 0; h < 2; h++) {
            const int rl = wm * 32 + mi * 16 + h * 8 + (lane >> 2);  // local row
            float lmin = 3.4e38f;
            #pragma unroll
            for (int ni = 0; ni < 8; ni++) {
                const int cl = wn * 64 + ni * 8 + (lane & 3) * 2;    // local col
                const float s0 = fmaf(-2.f, acc[mi][ni][h * 2 + 0], s_csq[cl + 0]);
                const float s1 = fmaf(-2.f, acc[mi][ni][h * 2 + 1], s_csq[cl + 1]);
                lmin = fminf(lmin, fminf(s0, s1));
                __nv_bfloat162 p;
                p.x = __float2bfloat16(s0);
                p.y = __float2bfloat16(s1);
                *(__nv_bfloat162*)(stage + rl * SROW + cl) = p;
            }
            lmin = fminf(lmin, __shfl_xor_sync(0xffffffffu, lmin, 1));
            lmin = fminf(lmin, __shfl_xor_sync(0xffffffffu, lmin, 2));
            if ((lane & 3) == 0)
                atomicMin(&g_rowmin[m0 + rl], fenc(lmin));
        }
    }
    __syncthreads();

    // coalesced write-out: thread t -> row t>>1, 64-col half (t&1), 8x16B
    {
        const int rr = tid >> 1;
        const int cc = (tid & 1) * 64;
        const uint4* src = (const uint4*)(stage + rr * SROW + cc);
        uint4* dst = (uint4*)(g_sc + (size_t)(m0 + rr) * NCENT + n0 + cc);
        #pragma unroll
        for (int i = 0; i < 8; i++) dst[i] = src[i];
    }
}

// ---------------------------------------------------------------------------
// Stage 2: bf16 candidate scan; cnt==1 fast path (provably exact), else exact
// fp32 rescore with the reference-faithful formula fmaf(-2,dot,xsq)+csq.
// ---------------------------------------------------------------------------
__global__ __launch_bounds__(256) void rescore_kernel(
    const float* __restrict__ x, const float* __restrict__ cent)
{
    __shared__ int   s_cand[256];
    __shared__ int   s_cnt;
    __shared__ float s_red[8];

    const int r = blockIdx.x, t = threadIdx.x;
    if (t == 0) s_cnt = 0;
    __syncthreads();

    const float thr = fdec(g_rowmin[r]) + MARGIN;
    const __nv_bfloat162* srow = (const __nv_bfloat162*)(g_sc + (size_t)r * NCENT);
    {
        const __nv_bfloat162 p0 = srow[t * 2 + 0];
        const __nv_bfloat162 p1 = srow[t * 2 + 1];
        const float v[4] = { __bfloat162float(p0.x), __bfloat162float(p0.y),
                             __bfloat162float(p1.x), __bfloat162float(p1.y) };
        #pragma unroll
        for (int j = 0; j < 4; j++) {
            if (v[j] <= thr) {
                int p = atomicAdd(&s_cnt, 1);
                if (p < 256) s_cand[p] = t * 4 + j;
            }
        }
    }
    __syncthreads();
    const int cnt = min(s_cnt, 256);

    if (cnt == 1) {               // unique candidate within margin: exact winner
        if (t == 0) g_idx[r] = s_cand[0];
        return;
    }

    const float* xr = x + (size_t)r * DIM;
    const float x0 = xr[t], x1 = xr[t + 256], x2 = xr[t + 512], x3 = xr[t + 768];
    const float xs = g_xsq[r];

    float best = 3.4e38f;
    int bidx = NCENT;
    for (int ci = 0; ci < cnt; ci++) {
        const int c = s_cand[ci];
        const float* cr = cent + (size_t)c * DIM;
        float a = fmaf(x0, cr[t], 0.f);
        a = fmaf(x1, cr[t + 256], a);
        a = fmaf(x2, cr[t + 512], a);
        a = fmaf(x3, cr[t + 768], a);
        #pragma unroll
        for (int o = 16; o > 0; o >>= 1)
            a += __shfl_xor_sync(0xffffffffu, a, o);
        if ((t & 31) == 0) s_red[t >> 5] = a;
        __syncthreads();
        if (t == 0) {
            float dot = s_red[0];
            #pragma unroll
            for (int w = 1; w < 8; w++) dot += s_red[w];
            const float d = fmaf(-2.f, dot, xs) + g_csq[c];
            if (d < best || (d == best && c < bidx)) { best = d; bidx = c; }
        }
        __syncthreads();
    }
    if (t == 0) g_idx[r] = bidx;
}

// ---------------------------------------------------------------------------
// Gather: out[r] = table[idx[r]] + bias (table L2-resident; write-bound).
// ---------------------------------------------------------------------------
__global__ __launch_bounds__(256) void gather_kernel(
    const float* __restrict__ table, const float* __restrict__ bias,
    float* __restrict__ out)
{
    const int r = blockIdx.x;
    const int idx = g_idx[r];
    const float4* src = (const float4*)(table + (size_t)idx * DIM);
    const float4* bv  = (const float4*)bias;
    float4* dst = (float4*)(out + (size_t)r * DIM);
    float4 a = src[threadIdx.x];
    float4 b = bv[threadIdx.x];
    dst[threadIdx.x] = make_float4(a.x + b.x, a.y + b.y, a.z + b.z, a.w + b.w);
}

// ---------------------------------------------------------------------------
extern "C" void kernel_launch(void* const* d_in, const int* in_sizes, int n_in,
                              void* d_out, int out_size) {
    const float* x     = (const float*)d_in[0];  // [4,4096,1024]
    const float* cent  = (const float*)d_in[1];  // [1024,1024]
    const float* table = (const float*)d_in[2];  // [1024,1024]
    const float* bias  = (const float*)d_in[3];  // [1024]
    float* out = (float*)d_out;

    cudaFuncSetAttribute(mma_score_kernel,
                         cudaFuncAttributeMaxDynamicSharedMemorySize, DSM_BYTES);

    prep_x_kernel<<<NROWS, 256>>>(x);
    prep_c_kernel<<<NCENT, 256>>>(cent);
    mma_score_kernel<<<dim3(NCENT / BN, NROWS / BM), 256, DSM_BYTES>>>();
    rescore_kernel<<<NROWS, 256>>>(x, cent);
    gather_kernel<<<NROWS, 256>>>(table, bias, out);
}

// round 10
// speedup vs baseline: 1.4911x; 1.0051x over previous
#include <cuda_runtime.h>
#include <cuda_bf16.h>
#include <cstdint>

#define NROWS 16384
#define DIM   1024
#define NCENT 1024
#define MARGIN 0.35f

#define BM 128
#define BN 128
#define BK 32
#define PAD_K 40   // bf16 elems per smem row (80B stride -> conflict-free ldmatrix)
#define NITER (DIM / BK)
#define NSTAGE 3
#define SROW 136   // score-stage smem row stride (bf16): 272B, 16B-aligned rows
#define MAXCAND 64

// ---- scratch (device globals only; no runtime allocation allowed) ----
__device__ float         g_xsq[NROWS];
__device__ float         g_csq[NCENT];
__device__ unsigned      g_rowmin[NROWS];               // ordered-key min of s
__device__ int           g_idx[NROWS];
__device__ __nv_bfloat16 g_xb[(size_t)NROWS * DIM];     // 32 MB
__device__ __nv_bfloat16 g_cb[(size_t)NCENT * DIM];     //  2 MB
__device__ __nv_bfloat16 g_sc[(size_t)NROWS * NCENT];   // 32 MB  s = -2dot+csq

// ---- ordered-float <-> uint key (monotone, handles negatives) ----
__device__ __forceinline__ unsigned fenc(float f) {
    unsigned u = __float_as_uint(f);
    return (u & 0x80000000u) ? ~u : (u | 0x80000000u);
}
__device__ __forceinline__ float fdec(unsigned k) {
    return (k & 0x80000000u) ? __uint_as_float(k & 0x7FFFFFFFu)
                             : __uint_as_float(~k);
}

// ---------------------------------------------------------------------------
// Prep: exact fp32 sum-of-squares + bf16 conversion + rowmin init.
// ---------------------------------------------------------------------------
__global__ __launch_bounds__(256) void prep_x_kernel(const float* __restrict__ x) {
    __shared__ float s[256];
    const int r = blockIdx.x, t = threadIdx.x;
    const float4 v = ((const float4*)(x + (size_t)r * DIM))[t];
    __nv_bfloat162 b01, b23;
    b01.x = __float2bfloat16(v.x); b01.y = __float2bfloat16(v.y);
    b23.x = __float2bfloat16(v.z); b23.y = __float2bfloat16(v.w);
    __nv_bfloat162* dst = (__nv_bfloat162*)(g_xb + (size_t)r * DIM);
    dst[t * 2 + 0] = b01;
    dst[t * 2 + 1] = b23;
    float acc = fmaf(v.x, v.x, 0.f);
    acc = fmaf(v.y, v.y, acc);
    acc = fmaf(v.z, v.z, acc);
    acc = fmaf(v.w, v.w, acc);
    s[t] = acc;
    __syncthreads();
    #pragma unroll
    for (int off = 128; off > 0; off >>= 1) {
        if (t < off) s[t] += s[t + off];
        __syncthreads();
    }
    if (t == 0) {
        g_xsq[r] = s[0];
        g_rowmin[r] = 0xFFFFFFFFu;   // max ordered key
    }
}

__global__ __launch_bounds__(256) void prep_c_kernel(const float* __restrict__ c) {
    __shared__ float s[256];
    const int r = blockIdx.x, t = threadIdx.x;
    const float4 v = ((const float4*)(c + (size_t)r * DIM))[t];
    __nv_bfloat162 b01, b23;
    b01.x = __float2bfloat16(v.x); b01.y = __float2bfloat16(v.y);
    b23.x = __float2bfloat16(v.z); b23.y = __float2bfloat16(v.w);
    __nv_bfloat162* dst = (__nv_bfloat162*)(g_cb + (size_t)r * DIM);
    dst[t * 2 + 0] = b01;
    dst[t * 2 + 1] = b23;
    float acc = fmaf(v.x, v.x, 0.f);
    acc = fmaf(v.y, v.y, acc);
    acc = fmaf(v.z, v.z, acc);
    acc = fmaf(v.w, v.w, acc);
    s[t] = acc;
    __syncthreads();
    #pragma unroll
    for (int off = 128; off > 0; off >>= 1) {
        if (t < off) s[t] += s[t + off];
        __syncthreads();
    }
    if (t == 0) g_csq[r] = s[0];
}

// ---------------------------------------------------------------------------
// Stage 1: bf16 HMMA GEMM, 128x128x32 tiles, 3-stage cp.async pipeline.
// Epilogue: s = -2dot+csq -> smem stage -> coalesced bf16 writes + rowmin.
// ---------------------------------------------------------------------------
__device__ __forceinline__ void cp16(uint32_t dst, const void* src) {
    asm volatile("cp.async.cg.shared.global [%0], [%1], 16;\n" :: "r"(dst), "l"(src));
}
__device__ __forceinline__ void ldsm4(uint32_t* r, uint32_t addr) {
    asm volatile("ldmatrix.sync.aligned.m8n8.x4.shared.b16 {%0,%1,%2,%3}, [%4];"
                 : "=r"(r[0]), "=r"(r[1]), "=r"(r[2]), "=r"(r[3]) : "r"(addr));
}
__device__ __forceinline__ void mma16816(float* c, const uint32_t* a, uint32_t b0, uint32_t b1) {
    asm volatile("mma.sync.aligned.m16n8k16.row.col.f32.bf16.bf16.f32 "
                 "{%0,%1,%2,%3}, {%4,%5,%6,%7}, {%8,%9}, {%0,%1,%2,%3};"
                 : "+f"(c[0]), "+f"(c[1]), "+f"(c[2]), "+f"(c[3])
                 : "r"(a[0]), "r"(a[1]), "r"(a[2]), "r"(a[3]), "r"(b0), "r"(b1));
}

#define TILE_BYTES2 (BM * PAD_K * 2)                 // 10240 B per tile buffer
#define DSM_BYTES (2 * NSTAGE * TILE_BYTES2)         // 61440 B

__global__ __launch_bounds__(256, 2) void mma_score_kernel() {
    extern __shared__ __align__(128) char dsm[];
    __shared__ float s_csq[BN];

    const int tid  = threadIdx.x;
    const int warp = tid >> 5, lane = tid & 31;
    const int wm = warp >> 1, wn = warp & 1;
    const int m0 = blockIdx.y * BM;
    const int n0 = blockIdx.x * BN;

    float acc[2][8][4];
    #pragma unroll
    for (int i = 0; i < 2; i++)
        #pragma unroll
        for (int j = 0; j < 8; j++)
            #pragma unroll
            for (int k = 0; k < 4; k++) acc[i][j][k] = 0.f;

    const uint32_t sbase = (uint32_t)__cvta_generic_to_shared(dsm);
    uint32_t sA[NSTAGE], sB[NSTAGE];
    #pragma unroll
    for (int s = 0; s < NSTAGE; s++) {
        sA[s] = sbase + s * TILE_BYTES2;
        sB[s] = sbase + (NSTAGE + s) * TILE_BYTES2;
    }

    if (tid < BN / 2)
        *(float2*)&s_csq[tid * 2] = *(const float2*)&g_csq[n0 + tid * 2];

    // tile loaders: thread -> row tid>>1, 32B half (tid&1)
    const int lr = tid >> 1;
    const int lc = (tid & 1) * 16;
    const uint32_t dOff = (uint32_t)(lr * PAD_K + lc) * 2;

    auto load_tile = [&](int buf, int k0) {
        const __nv_bfloat16* srcA = g_xb + (size_t)(m0 + lr) * DIM + k0 + lc;
        cp16(sA[buf] + dOff,      srcA);
        cp16(sA[buf] + dOff + 16, srcA + 8);
        const __nv_bfloat16* srcB = g_cb + (size_t)(n0 + lr) * DIM + k0 + lc;
        cp16(sB[buf] + dOff,      srcB);
        cp16(sB[buf] + dOff + 16, srcB + 8);
        asm volatile("cp.async.commit_group;");
    };

    load_tile(0, 0);
    load_tile(1, BK);

    // ldmatrix lane geometry
    const int a_row = (lane & 7) + ((lane >> 3) & 1) * 8;
    const int a_kof = (lane >> 4) * 8;
    const int b_row = (lane & 7) + (lane >> 4) * 8;
    const int b_kof = ((lane >> 3) & 1) * 8;

    #pragma unroll 1
    for (int kt = 0; kt < NITER; kt++) {
        const int buf = kt % NSTAGE;
        if (kt == NITER - 1) asm volatile("cp.async.wait_group 0;");
        else                 asm volatile("cp.async.wait_group 1;");
        __syncthreads();

        if (kt + 2 < NITER) load_tile((kt + 2) % NSTAGE, (kt + 2) * BK);

        #pragma unroll
        for (int ks = 0; ks < BK; ks += 16) {
            uint32_t af[2][4];
            #pragma unroll
            for (int mi = 0; mi < 2; mi++) {
                uint32_t addr = sA[buf] +
                    (uint32_t)((wm * 32 + mi * 16 + a_row) * PAD_K + ks + a_kof) * 2;
                ldsm4(af[mi], addr);
            }
            #pragma unroll
            for (int nt = 0; nt < 4; nt++) {
                uint32_t bf[4];
                uint32_t addr = sB[buf] +
                    (uint32_t)((wn * 64 + nt * 16 + b_row) * PAD_K + ks + b_kof) * 2;
                ldsm4(bf, addr);
                #pragma unroll
                for (int mi = 0; mi < 2; mi++) {
                    mma16816(acc[mi][2 * nt + 0], af[mi], bf[0], bf[1]);
                    mma16816(acc[mi][2 * nt + 1], af[mi], bf[2], bf[3]);
                }
            }
        }
    }
    __syncthreads();   // all warps done reading dsm before reuse as stage

    // ---- epilogue: stage bf16 scores in smem (reuse dsm), then coalesce ----
    __nv_bfloat16* stage = (__nv_bfloat16*)dsm;   // 128 x SROW bf16 = 34816 B

    #pragma unroll
    for (int mi = 0; mi < 2; mi++) {
        #pragma unroll
        for (int h = 0; h < 2; h++) {
            const int rl = wm * 32 + mi * 16 + h * 8 + (lane >> 2);  // local row
            float lmin = 3.4e38f;
            #pragma unroll
            for (int ni = 0; ni < 8; ni++) {
                const int cl = wn * 64 + ni * 8 + (lane & 3) * 2;    // local col
                const float s0 = fmaf(-2.f, acc[mi][ni][h * 2 + 0], s_csq[cl + 0]);
                const float s1 = fmaf(-2.f, acc[mi][ni][h * 2 + 1], s_csq[cl + 1]);
                lmin = fminf(lmin, fminf(s0, s1));
                __nv_bfloat162 p;
                p.x = __float2bfloat16(s0);
                p.y = __float2bfloat16(s1);
                *(__nv_bfloat162*)(stage + rl * SROW + cl) = p;
            }
            lmin = fminf(lmin, __shfl_xor_sync(0xffffffffu, lmin, 1));
            lmin = fminf(lmin, __shfl_xor_sync(0xffffffffu, lmin, 2));
            if ((lane & 3) == 0)
                atomicMin(&g_rowmin[m0 + rl], fenc(lmin));
        }
    }
    __syncthreads();

    // coalesced write-out: thread t -> row t>>1, 64-col half (t&1), 8x16B
    {
        const int rr = tid >> 1;
        const int cc = (tid & 1) * 64;
        const uint4* src = (const uint4*)(stage + rr * SROW + cc);
        uint4* dst = (uint4*)(g_sc + (size_t)(m0 + rr) * NCENT + n0 + cc);
        #pragma unroll
        for (int i = 0; i < 8; i++) dst[i] = src[i];
    }
}

// ---------------------------------------------------------------------------
// Stage 2: warp-per-row rescore. 8 rows per 256-thread block, no block
// barriers. Each lane scans 32 scores (full 1024 coverage). cnt==1 fast
// path; else exact fp32 rescore (reference-faithful fmaf(-2,dot,xsq)+csq,
// lowest-index tie-break).
// ---------------------------------------------------------------------------
__global__ __launch_bounds__(256) void rescore_kernel(
    const float* __restrict__ x, const float* __restrict__ cent)
{
    __shared__ int s_cand[8][MAXCAND];
    __shared__ int s_cnt[8];

    const int w = threadIdx.x >> 5, lane = threadIdx.x & 31;
    const int r = blockIdx.x * 8 + w;

    if (lane == 0) s_cnt[w] = 0;
    __syncwarp();

    const float thr = fdec(g_rowmin[r]) + MARGIN;
    // 32 scores per lane (64 B), full row coverage: indices lane*32 .. +31
    {
        const uint4* sp = (const uint4*)(g_sc + (size_t)r * NCENT) + lane * 4;
        uint4 q[4] = { sp[0], sp[1], sp[2], sp[3] };
        const __nv_bfloat162* pv = (const __nv_bfloat162*)q;
        #pragma unroll
        for (int i = 0; i < 16; i++) {
            const float v0 = __bfloat162float(pv[i].x);
            const float v1 = __bfloat162float(pv[i].y);
            if (v0 <= thr) {
                int p = atomicAdd(&s_cnt[w], 1);
                if (p < MAXCAND) s_cand[w][p] = lane * 32 + 2 * i;
            }
            if (v1 <= thr) {
                int p = atomicAdd(&s_cnt[w], 1);
                if (p < MAXCAND) s_cand[w][p] = lane * 32 + 2 * i + 1;
            }
        }
    }
    __syncwarp();
    const int cnt = min(s_cnt[w], MAXCAND);

    if (cnt == 1) {               // unique candidate within margin: exact winner
        if (lane == 0) g_idx[r] = s_cand[w][0];
        return;
    }

    // x row strided into regs: xv[j] = x[r][j*32 + lane] (coalesced per j)
    const float* xr = x + (size_t)r * DIM;
    float xv[32];
    #pragma unroll
    for (int j = 0; j < 32; j++) xv[j] = xr[j * 32 + lane];
    const float xs = g_xsq[r];

    float best = 3.4e38f;
    int bidx = NCENT;
    for (int ci = 0; ci < cnt; ci++) {
        const int c = s_cand[w][ci];
        const float* cr = cent + (size_t)c * DIM;
        float a = 0.f;
        #pragma unroll
        for (int j = 0; j < 32; j++)
            a = fmaf(xv[j], cr[j * 32 + lane], a);
        #pragma unroll
        for (int o = 16; o > 0; o >>= 1)
            a += __shfl_xor_sync(0xffffffffu, a, o);
        const float d = fmaf(-2.f, a, xs) + g_csq[c];
        if (d < best || (d == best && c < bidx)) { best = d; bidx = c; }
    }
    if (lane == 0) g_idx[r] = bidx;
}

// ---------------------------------------------------------------------------
// Gather: out[r] = table[idx[r]] + bias (table L2-resident; write-bound).
// ---------------------------------------------------------------------------
__global__ __launch_bounds__(256) void gather_kernel(
    const float* __restrict__ table, const float* __restrict__ bias,
    float* __restrict__ out)
{
    const int r = blockIdx.x;
    const int idx = g_idx[r];
    const float4* src = (const float4*)(table + (size_t)idx * DIM);
    const float4* bv  = (const float4*)bias;
    float4* dst = (float4*)(out + (size_t)r * DIM);
    float4 a = src[threadIdx.x];
    float4 b = bv[threadIdx.x];
    dst[threadIdx.x] = make_float4(a.x + b.x, a.y + b.y, a.z + b.z, a.w + b.w);
}

// ---------------------------------------------------------------------------
extern "C" void kernel_launch(void* const* d_in, const int* in_sizes, int n_in,
                              void* d_out, int out_size) {
    const float* x     = (const float*)d_in[0];  // [4,4096,1024]
    const float* cent  = (const float*)d_in[1];  // [1024,1024]
    const float* table = (const float*)d_in[2];  // [1024,1024]
    const float* bias  = (const float*)d_in[3];  // [1024]
    float* out = (float*)d_out;

    cudaFuncSetAttribute(mma_score_kernel,
                         cudaFuncAttributeMaxDynamicSharedMemorySize, DSM_BYTES);

    prep_x_kernel<<<NROWS, 256>>>(x);
    prep_c_kernel<<<NCENT, 256>>>(cent);
    mma_score_kernel<<<dim3(NCENT / BN, NROWS / BM), 256, DSM_BYTES>>>();
    rescore_kernel<<<NROWS / 8, 256>>>(x, cent);
    gather_kernel<<<NROWS, 256>>>(table, bias, out);
}

// round 11
// speedup vs baseline: 1.5737x; 1.0554x over previous
#include <cuda_runtime.h>
#include <cuda_bf16.h>
#include <cstdint>

#define NROWS 16384
#define DIM   1024
#define NCENT 1024
#define MARGIN 0.35f

#define BM 128
#define BN 128
#define BK 32
#define PAD_K 40   // bf16 elems per smem row (80B stride -> conflict-free ldmatrix)
#define NITER (DIM / BK)
#define SROW 136   // score-stage smem row stride (bf16): 272B, 16B-aligned rows
#define MAXCAND 64

// ---- scratch (device globals only; no runtime allocation allowed) ----
__device__ float         g_xsq[NROWS];
__device__ float         g_csq[NCENT];
__device__ unsigned      g_rowmin[NROWS];               // ordered-key min of s
__device__ int           g_idx[NROWS];
__device__ __nv_bfloat16 g_xb[(size_t)NROWS * DIM];     // 32 MB
__device__ __nv_bfloat16 g_cb[(size_t)NCENT * DIM];     //  2 MB
__device__ __nv_bfloat16 g_sc[(size_t)NROWS * NCENT];   // 32 MB  s = -2dot+csq

// ---- ordered-float <-> uint key (monotone, handles negatives) ----
__device__ __forceinline__ unsigned fenc(float f) {
    unsigned u = __float_as_uint(f);
    return (u & 0x80000000u) ? ~u : (u | 0x80000000u);
}
__device__ __forceinline__ float fdec(unsigned k) {
    return (k & 0x80000000u) ? __uint_as_float(k & 0x7FFFFFFFu)
                             : __uint_as_float(~k);
}

// ---------------------------------------------------------------------------
// Fused prep: blocks [0,NROWS) handle x rows, [NROWS,NROWS+NCENT) centroids.
// Exact fp32 sum-of-squares + bf16 conversion + rowmin init.
// ---------------------------------------------------------------------------
__global__ __launch_bounds__(256) void prep_kernel(
    const float* __restrict__ x, const float* __restrict__ c)
{
    __shared__ float s[256];
    const int b = blockIdx.x, t = threadIdx.x;
    const bool isX = (b < NROWS);
    const int r = isX ? b : (b - NROWS);
    const float* src = isX ? (x + (size_t)r * DIM) : (c + (size_t)r * DIM);
    __nv_bfloat162* dst = (__nv_bfloat162*)((isX ? g_xb : g_cb) + (size_t)r * DIM);

    const float4 v = ((const float4*)src)[t];
    __nv_bfloat162 b01, b23;
    b01.x = __float2bfloat16(v.x); b01.y = __float2bfloat16(v.y);
    b23.x = __float2bfloat16(v.z); b23.y = __float2bfloat16(v.w);
    dst[t * 2 + 0] = b01;
    dst[t * 2 + 1] = b23;

    float acc = fmaf(v.x, v.x, 0.f);
    acc = fmaf(v.y, v.y, acc);
    acc = fmaf(v.z, v.z, acc);
    acc = fmaf(v.w, v.w, acc);
    s[t] = acc;
    __syncthreads();
    #pragma unroll
    for (int off = 128; off > 0; off >>= 1) {
        if (t < off) s[t] += s[t + off];
        __syncthreads();
    }
    if (t == 0) {
        if (isX) {
            g_xsq[r] = s[0];
            g_rowmin[r] = 0xFFFFFFFFu;   // max ordered key
        } else {
            g_csq[r] = s[0];
        }
    }
}

// ---------------------------------------------------------------------------
// Stage 1: bf16 HMMA GEMM (R2/R7 measured-best mainloop), 128x128x32 tiles.
// Epilogue: s = -2dot+csq -> smem stage -> coalesced bf16 writes + rowmin.
// ---------------------------------------------------------------------------
__device__ __forceinline__ void cp16(uint32_t dst, const void* src) {
    asm volatile("cp.async.cg.shared.global [%0], [%1], 16;\n" :: "r"(dst), "l"(src));
}
__device__ __forceinline__ void ldsm4(uint32_t* r, uint32_t addr) {
    asm volatile("ldmatrix.sync.aligned.m8n8.x4.shared.b16 {%0,%1,%2,%3}, [%4];"
                 : "=r"(r[0]), "=r"(r[1]), "=r"(r[2]), "=r"(r[3]) : "r"(addr));
}
__device__ __forceinline__ void mma16816(float* c, const uint32_t* a, uint32_t b0, uint32_t b1) {
    asm volatile("mma.sync.aligned.m16n8k16.row.col.f32.bf16.bf16.f32 "
                 "{%0,%1,%2,%3}, {%4,%5,%6,%7}, {%8,%9}, {%0,%1,%2,%3};"
                 : "+f"(c[0]), "+f"(c[1]), "+f"(c[2]), "+f"(c[3])
                 : "r"(a[0]), "r"(a[1]), "r"(a[2]), "r"(a[3]), "r"(b0), "r"(b1));
}

#define TILE_HALF (BM * PAD_K)                 // bf16 elems per tile buffer
#define DSM_BYTES (4 * TILE_HALF * 2)          // 40960 B (2 bufs x (A+B))

__global__ __launch_bounds__(256, 2) void mma_score_kernel() {
    extern __shared__ __align__(128) char dsm[];
    __shared__ float s_csq[BN];

    const int tid  = threadIdx.x;
    const int warp = tid >> 5, lane = tid & 31;
    const int wm = warp >> 1, wn = warp & 1;
    const int m0 = blockIdx.y * BM;
    const int n0 = blockIdx.x * BN;

    float acc[2][8][4];
    #pragma unroll
    for (int i = 0; i < 2; i++)
        #pragma unroll
        for (int j = 0; j < 8; j++)
            #pragma unroll
            for (int k = 0; k < 4; k++) acc[i][j][k] = 0.f;

    const uint32_t sbase = (uint32_t)__cvta_generic_to_shared(dsm);
    uint32_t sA[2], sB[2];
    sA[0] = sbase;
    sA[1] = sbase + TILE_HALF * 2;
    sB[0] = sbase + 2 * TILE_HALF * 2;
    sB[1] = sbase + 3 * TILE_HALF * 2;

    if (tid < BN / 2)
        *(float2*)&s_csq[tid * 2] = *(const float2*)&g_csq[n0 + tid * 2];

    // tile loaders: thread -> row tid>>1, 32B half (tid&1)
    const int lr = tid >> 1;
    const int lc = (tid & 1) * 16;
    const uint32_t dOff = (uint32_t)(lr * PAD_K + lc) * 2;

    auto load_tile = [&](int buf, int k0) {
        const __nv_bfloat16* srcA = g_xb + (size_t)(m0 + lr) * DIM + k0 + lc;
        cp16(sA[buf] + dOff,      srcA);
        cp16(sA[buf] + dOff + 16, srcA + 8);
        const __nv_bfloat16* srcB = g_cb + (size_t)(n0 + lr) * DIM + k0 + lc;
        cp16(sB[buf] + dOff,      srcB);
        cp16(sB[buf] + dOff + 16, srcB + 8);
    };

    load_tile(0, 0);
    asm volatile("cp.async.commit_group;");
    asm volatile("cp.async.wait_group 0;");
    __syncthreads();

    // ldmatrix lane geometry
    const int a_row = (lane & 7) + ((lane >> 3) & 1) * 8;
    const int a_kof = (lane >> 4) * 8;
    const int b_row = (lane & 7) + (lane >> 4) * 8;
    const int b_kof = ((lane >> 3) & 1) * 8;

    #pragma unroll 1
    for (int kt = 0; kt < NITER; kt++) {
        const int buf = kt & 1;
        if (kt + 1 < NITER) {
            load_tile(buf ^ 1, (kt + 1) * BK);
            asm volatile("cp.async.commit_group;");
        }

        #pragma unroll
        for (int ks = 0; ks < BK; ks += 16) {
            uint32_t af[2][4];
            #pragma unroll
            for (int mi = 0; mi < 2; mi++) {
                uint32_t addr = sA[buf] +
                    (uint32_t)((wm * 32 + mi * 16 + a_row) * PAD_K + ks + a_kof) * 2;
                ldsm4(af[mi], addr);
            }
            #pragma unroll
            for (int nt = 0; nt < 4; nt++) {
                uint32_t bf[4];
                uint32_t addr = sB[buf] +
                    (uint32_t)((wn * 64 + nt * 16 + b_row) * PAD_K + ks + b_kof) * 2;
                ldsm4(bf, addr);
                #pragma unroll
                for (int mi = 0; mi < 2; mi++) {
                    mma16816(acc[mi][2 * nt + 0], af[mi], bf[0], bf[1]);
                    mma16816(acc[mi][2 * nt + 1], af[mi], bf[2], bf[3]);
                }
            }
        }

        asm volatile("cp.async.wait_group 0;");
        __syncthreads();
    }

    // ---- epilogue: stage bf16 scores in smem (reuse dsm), then coalesce ----
    __nv_bfloat16* stage = (__nv_bfloat16*)dsm;   // 128 x SROW bf16 = 34816 B

    #pragma unroll
    for (int mi = 0; mi < 2; mi++) {
        #pragma unroll
        for (int h = 0; h < 2; h++) {
            const int rl = wm * 32 + mi * 16 + h * 8 + (lane >> 2);  // local row
            float lmin = 3.4e38f;
            #pragma unroll
            for (int ni = 0; ni < 8; ni++) {
                const int cl = wn * 64 + ni * 8 + (lane & 3) * 2;    // local col
                const float s0 = fmaf(-2.f, acc[mi][ni][h * 2 + 0], s_csq[cl + 0]);
                const float s1 = fmaf(-2.f, acc[mi][ni][h * 2 + 1], s_csq[cl + 1]);
                lmin = fminf(lmin, fminf(s0, s1));
                __nv_bfloat162 p;
                p.x = __float2bfloat16(s0);
                p.y = __float2bfloat16(s1);
                *(__nv_bfloat162*)(stage + rl * SROW + cl) = p;
            }
            lmin = fminf(lmin, __shfl_xor_sync(0xffffffffu, lmin, 1));
            lmin = fminf(lmin, __shfl_xor_sync(0xffffffffu, lmin, 2));
            if ((lane & 3) == 0)
                atomicMin(&g_rowmin[m0 + rl], fenc(lmin));
        }
    }
    __syncthreads();

    // coalesced write-out: thread t -> row t>>1, 64-col half (t&1), 8x16B
    {
        const int rr = tid >> 1;
        const int cc = (tid & 1) * 64;
        const uint4* src = (const uint4*)(stage + rr * SROW + cc);
        uint4* dst = (uint4*)(g_sc + (size_t)(m0 + rr) * NCENT + n0 + cc);
        #pragma unroll
        for (int i = 0; i < 8; i++) dst[i] = src[i];
    }
}

// ---------------------------------------------------------------------------
// Stage 2: warp-per-row rescore. 8 rows per 256-thread block, no block
// barriers. Each lane scans 32 scores (full 1024 coverage). cnt==1 fast
// path; else exact fp32 rescore (reference-faithful fmaf(-2,dot,xsq)+csq,
// lowest-index tie-break).
// ---------------------------------------------------------------------------
__global__ __launch_bounds__(256) void rescore_kernel(
    const float* __restrict__ x, const float* __restrict__ cent)
{
    __shared__ int s_cand[8][MAXCAND];
    __shared__ int s_cnt[8];

    const int w = threadIdx.x >> 5, lane = threadIdx.x & 31;
    const int r = blockIdx.x * 8 + w;

    if (lane == 0) s_cnt[w] = 0;
    __syncwarp();

    const float thr = fdec(g_rowmin[r]) + MARGIN;
    // 32 scores per lane (64 B), full row coverage: indices lane*32 .. +31
    {
        const uint4* sp = (const uint4*)(g_sc + (size_t)r * NCENT) + lane * 4;
        uint4 q[4] = { sp[0], sp[1], sp[2], sp[3] };
        const __nv_bfloat162* pv = (const __nv_bfloat162*)q;
        #pragma unroll
        for (int i = 0; i < 16; i++) {
            const float v0 = __bfloat162float(pv[i].x);
            const float v1 = __bfloat162float(pv[i].y);
            if (v0 <= thr) {
                int p = atomicAdd(&s_cnt[w], 1);
                if (p < MAXCAND) s_cand[w][p] = lane * 32 + 2 * i;
            }
            if (v1 <= thr) {
                int p = atomicAdd(&s_cnt[w], 1);
                if (p < MAXCAND) s_cand[w][p] = lane * 32 + 2 * i + 1;
            }
        }
    }
    __syncwarp();
    const int cnt = min(s_cnt[w], MAXCAND);

    if (cnt == 1) {               // unique candidate within margin: exact winner
        if (lane == 0) g_idx[r] = s_cand[w][0];
        return;
    }

    // x row strided into regs: xv[j] = x[r][j*32 + lane] (coalesced per j)
    const float* xr = x + (size_t)r * DIM;
    float xv[32];
    #pragma unroll
    for (int j = 0; j < 32; j++) xv[j] = xr[j * 32 + lane];
    const float xs = g_xsq[r];

    float best = 3.4e38f;
    int bidx = NCENT;
    for (int ci = 0; ci < cnt; ci++) {
        const int c = s_cand[w][ci];
        const float* cr = cent + (size_t)c * DIM;
        float a = 0.f;
        #pragma unroll
        for (int j = 0; j < 32; j++)
            a = fmaf(xv[j], cr[j * 32 + lane], a);
        #pragma unroll
        for (int o = 16; o > 0; o >>= 1)
            a += __shfl_xor_sync(0xffffffffu, a, o);
        const float d = fmaf(-2.f, a, xs) + g_csq[c];
        if (d < best || (d == best && c < bidx)) { best = d; bidx = c; }
    }
    if (lane == 0) g_idx[r] = bidx;
}

// ---------------------------------------------------------------------------
// Gather: out[r] = table[idx[r]] + bias (table L2-resident; write-bound).
// ---------------------------------------------------------------------------
__global__ __launch_bounds__(256) void gather_kernel(
    const float* __restrict__ table, const float* __restrict__ bias,
    float* __restrict__ out)
{
    const int r = blockIdx.x;
    const int idx = g_idx[r];
    const float4* src = (const float4*)(table + (size_t)idx * DIM);
    const float4* bv  = (const float4*)bias;
    float4* dst = (float4*)(out + (size_t)r * DIM);
    float4 a = src[threadIdx.x];
    float4 b = bv[threadIdx.x];
    dst[threadIdx.x] = make_float4(a.x + b.x, a.y + b.y, a.z + b.z, a.w + b.w);
}

// ---------------------------------------------------------------------------
extern "C" void kernel_launch(void* const* d_in, const int* in_sizes, int n_in,
                              void* d_out, int out_size) {
    const float* x     = (const float*)d_in[0];  // [4,4096,1024]
    const float* cent  = (const float*)d_in[1];  // [1024,1024]
    const float* table = (const float*)d_in[2];  // [1024,1024]
    const float* bias  = (const float*)d_in[3];  // [1024]
    float* out = (float*)d_out;

    cudaFuncSetAttribute(mma_score_kernel,
                         cudaFuncAttributeMaxDynamicSharedMemorySize, DSM_BYTES);

    prep_kernel<<<NROWS + NCENT, 256>>>(x, cent);
    mma_score_kernel<<<dim3(NCENT / BN, NROWS / BM), 256, DSM_BYTES>>>();
    rescore_kernel<<<NROWS / 8, 256>>>(x, cent);
    gather_kernel<<<NROWS, 256>>>(table, bias, out);
}

// round 12
// speedup vs baseline: 1.6142x; 1.0257x over previous
#include <cuda_runtime.h>
#include <cuda_bf16.h>
#include <cstdint>

#define NROWS 16384
#define DIM   1024
#define NCENT 1024
#define MARGIN 0.35f

#define BM 128
#define BN 128
#define BK 32
#define PAD_K 40   // bf16 elems per smem row (80B stride -> conflict-free ldmatrix)
#define NITER (DIM / BK)
#define SROW 136   // score-stage smem row stride (bf16): 272B, 16B-aligned rows
#define MAXCAND 64

// ---- scratch (device globals only; no runtime allocation allowed) ----
__device__ float         g_xsq[NROWS];
__device__ float         g_csq[NCENT];
__device__ unsigned      g_rowmin[NROWS];               // ordered-key min of s
__device__ __nv_bfloat16 g_xb[(size_t)NROWS * DIM];     // 32 MB
__device__ __nv_bfloat16 g_cb[(size_t)NCENT * DIM];     //  2 MB
__device__ __nv_bfloat16 g_sc[(size_t)NROWS * NCENT];   // 32 MB  s = -2dot+csq

// ---- ordered-float <-> uint key (monotone, handles negatives) ----
__device__ __forceinline__ unsigned fenc(float f) {
    unsigned u = __float_as_uint(f);
    return (u & 0x80000000u) ? ~u : (u | 0x80000000u);
}
__device__ __forceinline__ float fdec(unsigned k) {
    return (k & 0x80000000u) ? __uint_as_float(k & 0x7FFFFFFFu)
                             : __uint_as_float(~k);
}

// ---------------------------------------------------------------------------
// Fused prep: blocks [0,NROWS) handle x rows, [NROWS,NROWS+NCENT) centroids.
// Exact fp32 sum-of-squares + bf16 conversion + rowmin init.
// ---------------------------------------------------------------------------
__global__ __launch_bounds__(256) void prep_kernel(
    const float* __restrict__ x, const float* __restrict__ c)
{
    __shared__ float s[256];
    const int b = blockIdx.x, t = threadIdx.x;
    const bool isX = (b < NROWS);
    const int r = isX ? b : (b - NROWS);
    const float* src = isX ? (x + (size_t)r * DIM) : (c + (size_t)r * DIM);
    __nv_bfloat162* dst = (__nv_bfloat162*)((isX ? g_xb : g_cb) + (size_t)r * DIM);

    const float4 v = ((const float4*)src)[t];
    __nv_bfloat162 b01, b23;
    b01.x = __float2bfloat16(v.x); b01.y = __float2bfloat16(v.y);
    b23.x = __float2bfloat16(v.z); b23.y = __float2bfloat16(v.w);
    dst[t * 2 + 0] = b01;
    dst[t * 2 + 1] = b23;

    float acc = fmaf(v.x, v.x, 0.f);
    acc = fmaf(v.y, v.y, acc);
    acc = fmaf(v.z, v.z, acc);
    acc = fmaf(v.w, v.w, acc);
    s[t] = acc;
    __syncthreads();
    #pragma unroll
    for (int off = 128; off > 0; off >>= 1) {
        if (t < off) s[t] += s[t + off];
        __syncthreads();
    }
    if (t == 0) {
        if (isX) {
            g_xsq[r] = s[0];
            g_rowmin[r] = 0xFFFFFFFFu;   // max ordered key
        } else {
            g_csq[r] = s[0];
        }
    }
}

// ---------------------------------------------------------------------------
// Stage 1: bf16 HMMA GEMM (R2/R7 measured-best mainloop), 128x128x32 tiles.
// Epilogue: s = -2dot+csq -> smem stage -> coalesced bf16 writes + rowmin.
// ---------------------------------------------------------------------------
__device__ __forceinline__ void cp16(uint32_t dst, const void* src) {
    asm volatile("cp.async.cg.shared.global [%0], [%1], 16;\n" :: "r"(dst), "l"(src));
}
__device__ __forceinline__ void ldsm4(uint32_t* r, uint32_t addr) {
    asm volatile("ldmatrix.sync.aligned.m8n8.x4.shared.b16 {%0,%1,%2,%3}, [%4];"
                 : "=r"(r[0]), "=r"(r[1]), "=r"(r[2]), "=r"(r[3]) : "r"(addr));
}
__device__ __forceinline__ void mma16816(float* c, const uint32_t* a, uint32_t b0, uint32_t b1) {
    asm volatile("mma.sync.aligned.m16n8k16.row.col.f32.bf16.bf16.f32 "
                 "{%0,%1,%2,%3}, {%4,%5,%6,%7}, {%8,%9}, {%0,%1,%2,%3};"
                 : "+f"(c[0]), "+f"(c[1]), "+f"(c[2]), "+f"(c[3])
                 : "r"(a[0]), "r"(a[1]), "r"(a[2]), "r"(a[3]), "r"(b0), "r"(b1));
}

#define TILE_HALF (BM * PAD_K)                 // bf16 elems per tile buffer
#define DSM_BYTES (4 * TILE_HALF * 2)          // 40960 B (2 bufs x (A+B))

__global__ __launch_bounds__(256, 2) void mma_score_kernel() {
    extern __shared__ __align__(128) char dsm[];
    __shared__ float s_csq[BN];

    const int tid  = threadIdx.x;
    const int warp = tid >> 5, lane = tid & 31;
    const int wm = warp >> 1, wn = warp & 1;
    const int m0 = blockIdx.y * BM;
    const int n0 = blockIdx.x * BN;

    float acc[2][8][4];
    #pragma unroll
    for (int i = 0; i < 2; i++)
        #pragma unroll
        for (int j = 0; j < 8; j++)
            #pragma unroll
            for (int k = 0; k < 4; k++) acc[i][j][k] = 0.f;

    const uint32_t sbase = (uint32_t)__cvta_generic_to_shared(dsm);
    uint32_t sA[2], sB[2];
    sA[0] = sbase;
    sA[1] = sbase + TILE_HALF * 2;
    sB[0] = sbase + 2 * TILE_HALF * 2;
    sB[1] = sbase + 3 * TILE_HALF * 2;

    if (tid < BN / 2)
        *(float2*)&s_csq[tid * 2] = *(const float2*)&g_csq[n0 + tid * 2];

    // tile loaders: thread -> row tid>>1, 32B half (tid&1)
    const int lr = tid >> 1;
    const int lc = (tid & 1) * 16;
    const uint32_t dOff = (uint32_t)(lr * PAD_K + lc) * 2;

    auto load_tile = [&](int buf, int k0) {
        const __nv_bfloat16* srcA = g_xb + (size_t)(m0 + lr) * DIM + k0 + lc;
        cp16(sA[buf] + dOff,      srcA);
        cp16(sA[buf] + dOff + 16, srcA + 8);
        const __nv_bfloat16* srcB = g_cb + (size_t)(n0 + lr) * DIM + k0 + lc;
        cp16(sB[buf] + dOff,      srcB);
        cp16(sB[buf] + dOff + 16, srcB + 8);
    };

    load_tile(0, 0);
    asm volatile("cp.async.commit_group;");
    asm volatile("cp.async.wait_group 0;");
    __syncthreads();

    // ldmatrix lane geometry
    const int a_row = (lane & 7) + ((lane >> 3) & 1) * 8;
    const int a_kof = (lane >> 4) * 8;
    const int b_row = (lane & 7) + (lane >> 4) * 8;
    const int b_kof = ((lane >> 3) & 1) * 8;

    #pragma unroll 1
    for (int kt = 0; kt < NITER; kt++) {
        const int buf = kt & 1;
        if (kt + 1 < NITER) {
            load_tile(buf ^ 1, (kt + 1) * BK);
            asm volatile("cp.async.commit_group;");
        }

        #pragma unroll
        for (int ks = 0; ks < BK; ks += 16) {
            uint32_t af[2][4];
            #pragma unroll
            for (int mi = 0; mi < 2; mi++) {
                uint32_t addr = sA[buf] +
                    (uint32_t)((wm * 32 + mi * 16 + a_row) * PAD_K + ks + a_kof) * 2;
                ldsm4(af[mi], addr);
            }
            #pragma unroll
            for (int nt = 0; nt < 4; nt++) {
                uint32_t bf[4];
                uint32_t addr = sB[buf] +
                    (uint32_t)((wn * 64 + nt * 16 + b_row) * PAD_K + ks + b_kof) * 2;
                ldsm4(bf, addr);
                #pragma unroll
                for (int mi = 0; mi < 2; mi++) {
                    mma16816(acc[mi][2 * nt + 0], af[mi], bf[0], bf[1]);
                    mma16816(acc[mi][2 * nt + 1], af[mi], bf[2], bf[3]);
                }
            }
        }

        asm volatile("cp.async.wait_group 0;");
        __syncthreads();
    }

    // ---- epilogue: stage bf16 scores in smem (reuse dsm), then coalesce ----
    __nv_bfloat16* stage = (__nv_bfloat16*)dsm;   // 128 x SROW bf16 = 34816 B

    #pragma unroll
    for (int mi = 0; mi < 2; mi++) {
        #pragma unroll
        for (int h = 0; h < 2; h++) {
            const int rl = wm * 32 + mi * 16 + h * 8 + (lane >> 2);  // local row
            float lmin = 3.4e38f;
            #pragma unroll
            for (int ni = 0; ni < 8; ni++) {
                const int cl = wn * 64 + ni * 8 + (lane & 3) * 2;    // local col
                const float s0 = fmaf(-2.f, acc[mi][ni][h * 2 + 0], s_csq[cl + 0]);
                const float s1 = fmaf(-2.f, acc[mi][ni][h * 2 + 1], s_csq[cl + 1]);
                lmin = fminf(lmin, fminf(s0, s1));
                __nv_bfloat162 p;
                p.x = __float2bfloat16(s0);
                p.y = __float2bfloat16(s1);
                *(__nv_bfloat162*)(stage + rl * SROW + cl) = p;
            }
            lmin = fminf(lmin, __shfl_xor_sync(0xffffffffu, lmin, 1));
            lmin = fminf(lmin, __shfl_xor_sync(0xffffffffu, lmin, 2));
            if ((lane & 3) == 0)
                atomicMin(&g_rowmin[m0 + rl], fenc(lmin));
        }
    }
    __syncthreads();

    // coalesced write-out: thread t -> row t>>1, 64-col half (t&1), 8x16B
    {
        const int rr = tid >> 1;
        const int cc = (tid & 1) * 64;
        const uint4* src = (const uint4*)(stage + rr * SROW + cc);
        uint4* dst = (uint4*)(g_sc + (size_t)(m0 + rr) * NCENT + n0 + cc);
        #pragma unroll
        for (int i = 0; i < 8; i++) dst[i] = src[i];
    }
}

// ---------------------------------------------------------------------------
// Stage 2 (fused): warp-per-row rescore + gather. 8 rows per block, no block
// barriers. Candidate scan (32 scores/lane, full coverage); cnt==1 fast path;
// exact fp32 rescore otherwise (reference-faithful fmaf(-2,dot,xsq)+csq,
// lowest-index tie-break). Winner's table row + bias written by same warp.
// ---------------------------------------------------------------------------
__global__ __launch_bounds__(256) void rescore_gather_kernel(
    const float* __restrict__ x, const float* __restrict__ cent,
    const float* __restrict__ table, const float* __restrict__ bias,
    float* __restrict__ out)
{
    __shared__ int s_cand[8][MAXCAND];
    __shared__ int s_cnt[8];

    const int w = threadIdx.x >> 5, lane = threadIdx.x & 31;
    const int r = blockIdx.x * 8 + w;

    if (lane == 0) s_cnt[w] = 0;
    __syncwarp();

    const float thr = fdec(g_rowmin[r]) + MARGIN;
    // 32 scores per lane (64 B), full row coverage: indices lane*32 .. +31
    {
        const uint4* sp = (const uint4*)(g_sc + (size_t)r * NCENT) + lane * 4;
        uint4 q[4] = { sp[0], sp[1], sp[2], sp[3] };
        const __nv_bfloat162* pv = (const __nv_bfloat162*)q;
        #pragma unroll
        for (int i = 0; i < 16; i++) {
            const float v0 = __bfloat162float(pv[i].x);
            const float v1 = __bfloat162float(pv[i].y);
            if (v0 <= thr) {
                int p = atomicAdd(&s_cnt[w], 1);
                if (p < MAXCAND) s_cand[w][p] = lane * 32 + 2 * i;
            }
            if (v1 <= thr) {
                int p = atomicAdd(&s_cnt[w], 1);
                if (p < MAXCAND) s_cand[w][p] = lane * 32 + 2 * i + 1;
            }
        }
    }
    __syncwarp();
    const int cnt = min(s_cnt[w], MAXCAND);

    int bidx;
    if (cnt == 1) {               // unique candidate within margin: exact winner
        bidx = s_cand[w][0];
    } else {
        // x row strided into regs: xv[j] = x[r][j*32 + lane] (coalesced per j)
        const float* xr = x + (size_t)r * DIM;
        float xv[32];
        #pragma unroll
        for (int j = 0; j < 32; j++) xv[j] = xr[j * 32 + lane];
        const float xs = g_xsq[r];

        float best = 3.4e38f;
        bidx = NCENT;
        for (int ci = 0; ci < cnt; ci++) {
            const int c = s_cand[w][ci];
            const float* cr = cent + (size_t)c * DIM;
            float a = 0.f;
            #pragma unroll
            for (int j = 0; j < 32; j++)
                a = fmaf(xv[j], cr[j * 32 + lane], a);
            #pragma unroll
            for (int o = 16; o > 0; o >>= 1)
                a += __shfl_xor_sync(0xffffffffu, a, o);
            const float d = fmaf(-2.f, a, xs) + g_csq[c];
            if (d < best || (d == best && c < bidx)) { best = d; bidx = c; }
        }
    }

    // gather: out[r] = table[bidx] + bias (warp-coalesced float4 sweeps)
    const float4* src = (const float4*)(table + (size_t)bidx * DIM);
    const float4* bv  = (const float4*)bias;
    float4* dst = (float4*)(out + (size_t)r * DIM);
    #pragma unroll
    for (int j = 0; j < 8; j++) {
        const float4 a = src[j * 32 + lane];
        const float4 b = bv[j * 32 + lane];
        dst[j * 32 + lane] = make_float4(a.x + b.x, a.y + b.y, a.z + b.z, a.w + b.w);
    }
}

// ---------------------------------------------------------------------------
extern "C" void kernel_launch(void* const* d_in, const int* in_sizes, int n_in,
                              void* d_out, int out_size) {
    const float* x     = (const float*)d_in[0];  // [4,4096,1024]
    const float* cent  = (const float*)d_in[1];  // [1024,1024]
    const float* table = (const float*)d_in[2];  // [1024,1024]
    const float* bias  = (const float*)d_in[3];  // [1024]
    float* out = (float*)d_out;

    cudaFuncSetAttribute(mma_score_kernel,
                         cudaFuncAttributeMaxDynamicSharedMemorySize, DSM_BYTES);

    prep_kernel<<<NROWS + NCENT, 256>>>(x, cent);
    mma_score_kernel<<<dim3(NCENT / BN, NROWS / BM), 256, DSM_BYTES>>>();
    rescore_gather_kernel<<<NROWS / 8, 256>>>(x, cent, table, bias, out);
}

// round 13
// speedup vs baseline: 1.6826x; 1.0424x over previous
#include <cuda_runtime.h>
#include <cuda_bf16.h>
#include <cstdint>

#define NROWS 16384
#define DIM   1024
#define NCENT 1024
#define MARGIN 0.35f

#define BM 128
#define BN 128
#define BK 32
#define PAD_K 40   // bf16 elems per smem row (80B stride -> conflict-free ldmatrix)
#define NITER (DIM / BK)
#define SROW 136   // score-stage smem row stride (bf16): 272B, 16B-aligned rows
#define MAXCAND 64

// ---- scratch (device globals only; no runtime allocation allowed) ----
__device__ float         g_xsq[NROWS];
__device__ float         g_csq[NCENT];
__device__ unsigned      g_rowmin[NROWS];               // ordered-key min of s
__device__ __nv_bfloat16 g_xb[(size_t)NROWS * DIM];     // 32 MB
__device__ __nv_bfloat16 g_cb[(size_t)NCENT * DIM];     //  2 MB
__device__ __nv_bfloat16 g_sc[(size_t)NROWS * NCENT];   // 32 MB  s = -2dot+csq

// ---- ordered-float <-> uint key (monotone, handles negatives) ----
__device__ __forceinline__ unsigned fenc(float f) {
    unsigned u = __float_as_uint(f);
    return (u & 0x80000000u) ? ~u : (u | 0x80000000u);
}
__device__ __forceinline__ float fdec(unsigned k) {
    return (k & 0x80000000u) ? __uint_as_float(k & 0x7FFFFFFFu)
                             : __uint_as_float(~k);
}

// ---------------------------------------------------------------------------
// Prep, warp-per-row: 8 rows per 256-thread block, no block barriers.
// Rows [0,NROWS) = x, [NROWS,NROWS+NCENT) = centroids.
// Exact fp32 sum-of-squares (warp butterfly) + bf16 conversion + rowmin init.
// ---------------------------------------------------------------------------
__global__ __launch_bounds__(256) void prep_kernel(
    const float* __restrict__ x, const float* __restrict__ c)
{
    const int w = threadIdx.x >> 5, lane = threadIdx.x & 31;
    const int row = blockIdx.x * 8 + w;
    const bool isX = (row < NROWS);
    const int r = isX ? row : (row - NROWS);
    const float4* src = (const float4*)((isX ? x : c) + (size_t)r * DIM);
    __nv_bfloat162* dst = (__nv_bfloat162*)((isX ? g_xb : g_cb) + (size_t)r * DIM);

    float acc = 0.f;
    #pragma unroll
    for (int j = 0; j < 8; j++) {
        const int e = j * 32 + lane;          // float4 index within row
        const float4 v = src[e];
        __nv_bfloat162 b01, b23;
        b01.x = __float2bfloat16(v.x); b01.y = __float2bfloat16(v.y);
        b23.x = __float2bfloat16(v.z); b23.y = __float2bfloat16(v.w);
        dst[e * 2 + 0] = b01;
        dst[e * 2 + 1] = b23;
        acc = fmaf(v.x, v.x, acc);
        acc = fmaf(v.y, v.y, acc);
        acc = fmaf(v.z, v.z, acc);
        acc = fmaf(v.w, v.w, acc);
    }
    #pragma unroll
    for (int o = 16; o > 0; o >>= 1)
        acc += __shfl_xor_sync(0xffffffffu, acc, o);

    if (lane == 0) {
        if (isX) {
            g_xsq[r] = acc;
            g_rowmin[r] = 0xFFFFFFFFu;   // max ordered key
        } else {
            g_csq[r] = acc;
        }
    }
}

// ---------------------------------------------------------------------------
// Stage 1: bf16 HMMA GEMM (R2/R7 measured-best mainloop), 128x128x32 tiles.
// Epilogue: s = -2dot+csq -> smem stage -> coalesced bf16 writes + rowmin.
// ---------------------------------------------------------------------------
__device__ __forceinline__ void cp16(uint32_t dst, const void* src) {
    asm volatile("cp.async.cg.shared.global [%0], [%1], 16;\n" :: "r"(dst), "l"(src));
}
__device__ __forceinline__ void ldsm4(uint32_t* r, uint32_t addr) {
    asm volatile("ldmatrix.sync.aligned.m8n8.x4.shared.b16 {%0,%1,%2,%3}, [%4];"
                 : "=r"(r[0]), "=r"(r[1]), "=r"(r[2]), "=r"(r[3]) : "r"(addr));
}
__device__ __forceinline__ void mma16816(float* c, const uint32_t* a, uint32_t b0, uint32_t b1) {
    asm volatile("mma.sync.aligned.m16n8k16.row.col.f32.bf16.bf16.f32 "
                 "{%0,%1,%2,%3}, {%4,%5,%6,%7}, {%8,%9}, {%0,%1,%2,%3};"
                 : "+f"(c[0]), "+f"(c[1]), "+f"(c[2]), "+f"(c[3])
                 : "r"(a[0]), "r"(a[1]), "r"(a[2]), "r"(a[3]), "r"(b0), "r"(b1));
}

#define TILE_HALF (BM * PAD_K)                 // bf16 elems per tile buffer
#define DSM_BYTES (4 * TILE_HALF * 2)          // 40960 B (2 bufs x (A+B))

__global__ __launch_bounds__(256, 2) void mma_score_kernel() {
    extern __shared__ __align__(128) char dsm[];
    __shared__ float s_csq[BN];

    const int tid  = threadIdx.x;
    const int warp = tid >> 5, lane = tid & 31;
    const int wm = warp >> 1, wn = warp & 1;
    const int m0 = blockIdx.y * BM;
    const int n0 = blockIdx.x * BN;

    float acc[2][8][4];
    #pragma unroll
    for (int i = 0; i < 2; i++)
        #pragma unroll
        for (int j = 0; j < 8; j++)
            #pragma unroll
            for (int k = 0; k < 4; k++) acc[i][j][k] = 0.f;

    const uint32_t sbase = (uint32_t)__cvta_generic_to_shared(dsm);
    uint32_t sA[2], sB[2];
    sA[0] = sbase;
    sA[1] = sbase + TILE_HALF * 2;
    sB[0] = sbase + 2 * TILE_HALF * 2;
    sB[1] = sbase + 3 * TILE_HALF * 2;

    if (tid < BN / 2)
        *(float2*)&s_csq[tid * 2] = *(const float2*)&g_csq[n0 + tid * 2];

    // tile loaders: thread -> row tid>>1, 32B half (tid&1)
    const int lr = tid >> 1;
    const int lc = (tid & 1) * 16;
    const uint32_t dOff = (uint32_t)(lr * PAD_K + lc) * 2;

    auto load_tile = [&](int buf, int k0) {
        const __nv_bfloat16* srcA = g_xb + (size_t)(m0 + lr) * DIM + k0 + lc;
        cp16(sA[buf] + dOff,      srcA);
        cp16(sA[buf] + dOff + 16, srcA + 8);
        const __nv_bfloat16* srcB = g_cb + (size_t)(n0 + lr) * DIM + k0 + lc;
        cp16(sB[buf] + dOff,      srcB);
        cp16(sB[buf] + dOff + 16, srcB + 8);
    };

    load_tile(0, 0);
    asm volatile("cp.async.commit_group;");
    asm volatile("cp.async.wait_group 0;");
    __syncthreads();

    // ldmatrix lane geometry
    const int a_row = (lane & 7) + ((lane >> 3) & 1) * 8;
    const int a_kof = (lane >> 4) * 8;
    const int b_row = (lane & 7) + (lane >> 4) * 8;
    const int b_kof = ((lane >> 3) & 1) * 8;

    #pragma unroll 1
    for (int kt = 0; kt < NITER; kt++) {
        const int buf = kt & 1;
        if (kt + 1 < NITER) {
            load_tile(buf ^ 1, (kt + 1) * BK);
            asm volatile("cp.async.commit_group;");
        }

        #pragma unroll
        for (int ks = 0; ks < BK; ks += 16) {
            uint32_t af[2][4];
            #pragma unroll
            for (int mi = 0; mi < 2; mi++) {
                uint32_t addr = sA[buf] +
                    (uint32_t)((wm * 32 + mi * 16 + a_row) * PAD_K + ks + a_kof) * 2;
                ldsm4(af[mi], addr);
            }
            #pragma unroll
            for (int nt = 0; nt < 4; nt++) {
                uint32_t bf[4];
                uint32_t addr = sB[buf] +
                    (uint32_t)((wn * 64 + nt * 16 + b_row) * PAD_K + ks + b_kof) * 2;
                ldsm4(bf, addr);
                #pragma unroll
                for (int mi = 0; mi < 2; mi++) {
                    mma16816(acc[mi][2 * nt + 0], af[mi], bf[0], bf[1]);
                    mma16816(acc[mi][2 * nt + 1], af[mi], bf[2], bf[3]);
                }
            }
        }

        asm volatile("cp.async.wait_group 0;");
        __syncthreads();
    }

    // ---- epilogue: stage bf16 scores in smem (reuse dsm), then coalesce ----
    __nv_bfloat16* stage = (__nv_bfloat16*)dsm;   // 128 x SROW bf16 = 34816 B

    #pragma unroll
    for (int mi = 0; mi < 2; mi++) {
        #pragma unroll
        for (int h = 0; h < 2; h++) {
            const int rl = wm * 32 + mi * 16 + h * 8 + (lane >> 2);  // local row
            float lmin = 3.4e38f;
            #pragma unroll
            for (int ni = 0; ni < 8; ni++) {
                const int cl = wn * 64 + ni * 8 + (lane & 3) * 2;    // local col
                const float s0 = fmaf(-2.f, acc[mi][ni][h * 2 + 0], s_csq[cl + 0]);
                const float s1 = fmaf(-2.f, acc[mi][ni][h * 2 + 1], s_csq[cl + 1]);
                lmin = fminf(lmin, fminf(s0, s1));
                __nv_bfloat162 p;
                p.x = __float2bfloat16(s0);
                p.y = __float2bfloat16(s1);
                *(__nv_bfloat162*)(stage + rl * SROW + cl) = p;
            }
            lmin = fminf(lmin, __shfl_xor_sync(0xffffffffu, lmin, 1));
            lmin = fminf(lmin, __shfl_xor_sync(0xffffffffu, lmin, 2));
            if ((lane & 3) == 0)
                atomicMin(&g_rowmin[m0 + rl], fenc(lmin));
        }
    }
    __syncthreads();

    // coalesced write-out: thread t -> row t>>1, 64-col half (t&1), 8x16B
    {
        const int rr = tid >> 1;
        const int cc = (tid & 1) * 64;
        const uint4* src = (const uint4*)(stage + rr * SROW + cc);
        uint4* dst = (uint4*)(g_sc + (size_t)(m0 + rr) * NCENT + n0 + cc);
        #pragma unroll
        for (int i = 0; i < 8; i++) dst[i] = src[i];
    }
}

// ---------------------------------------------------------------------------
// Stage 2 (fused): warp-per-row rescore + gather. 8 rows per block, no block
// barriers. Candidate scan (32 scores/lane, full coverage); cnt==1 fast path;
// exact fp32 rescore otherwise (reference-faithful fmaf(-2,dot,xsq)+csq,
// lowest-index tie-break). Winner's table row + bias written by same warp.
// ---------------------------------------------------------------------------
__global__ __launch_bounds__(256) void rescore_gather_kernel(
    const float* __restrict__ x, const float* __restrict__ cent,
    const float* __restrict__ table, const float* __restrict__ bias,
    float* __restrict__ out)
{
    __shared__ int s_cand[8][MAXCAND];
    __shared__ int s_cnt[8];

    const int w = threadIdx.x >> 5, lane = threadIdx.x & 31;
    const int r = blockIdx.x * 8 + w;

    if (lane == 0) s_cnt[w] = 0;
    __syncwarp();

    const float thr = fdec(g_rowmin[r]) + MARGIN;
    // 32 scores per lane (64 B), full row coverage: indices lane*32 .. +31
    {
        const uint4* sp = (const uint4*)(g_sc + (size_t)r * NCENT) + lane * 4;
        uint4 q[4] = { sp[0], sp[1], sp[2], sp[3] };
        const __nv_bfloat162* pv = (const __nv_bfloat162*)q;
        #pragma unroll
        for (int i = 0; i < 16; i++) {
            const float v0 = __bfloat162float(pv[i].x);
            const float v1 = __bfloat162float(pv[i].y);
            if (v0 <= thr) {
                int p = atomicAdd(&s_cnt[w], 1);
                if (p < MAXCAND) s_cand[w][p] = lane * 32 + 2 * i;
            }
            if (v1 <= thr) {
                int p = atomicAdd(&s_cnt[w], 1);
                if (p < MAXCAND) s_cand[w][p] = lane * 32 + 2 * i + 1;
            }
        }
    }
    __syncwarp();
    const int cnt = min(s_cnt[w], MAXCAND);

    int bidx;
    if (cnt == 1) {               // unique candidate within margin: exact winner
        bidx = s_cand[w][0];
    } else {
        // x row strided into regs: xv[j] = x[r][j*32 + lane] (coalesced per j)
        const float* xr = x + (size_t)r * DIM;
        float xv[32];
        #pragma unroll
        for (int j = 0; j < 32; j++) xv[j] = xr[j * 32 + lane];
        const float xs = g_xsq[r];

        float best = 3.4e38f;
        bidx = NCENT;
        for (int ci = 0; ci < cnt; ci++) {
            const int c = s_cand[w][ci];
            const float* cr = cent + (size_t)c * DIM;
            float a = 0.f;
            #pragma unroll
            for (int j = 0; j < 32; j++)
                a = fmaf(xv[j], cr[j * 32 + lane], a);
            #pragma unroll
            for (int o = 16; o > 0; o >>= 1)
                a += __shfl_xor_sync(0xffffffffu, a, o);
            const float d = fmaf(-2.f, a, xs) + g_csq[c];
            if (d < best || (d == best && c < bidx)) { best = d; bidx = c; }
        }
    }

    // gather: out[r] = table[bidx] + bias (warp-coalesced float4 sweeps)
    const float4* src = (const float4*)(table + (size_t)bidx * DIM);
    const float4* bv  = (const float4*)bias;
    float4* dst = (float4*)(out + (size_t)r * DIM);
    #pragma unroll
    for (int j = 0; j < 8; j++) {
        const float4 a = src[j * 32 + lane];
        const float4 b = bv[j * 32 + lane];
        dst[j * 32 + lane] = make_float4(a.x + b.x, a.y + b.y, a.z + b.z, a.w + b.w);
    }
}

// ---------------------------------------------------------------------------
extern "C" void kernel_launch(void* const* d_in, const int* in_sizes, int n_in,
                              void* d_out, int out_size) {
    const float* x     = (const float*)d_in[0];  // [4,4096,1024]
    const float* cent  = (const float*)d_in[1];  // [1024,1024]
    const float* table = (const float*)d_in[2];  // [1024,1024]
    const float* bias  = (const float*)d_in[3];  // [1024]
    float* out = (float*)d_out;

    cudaFuncSetAttribute(mma_score_kernel,
                         cudaFuncAttributeMaxDynamicSharedMemorySize, DSM_BYTES);

    prep_kernel<<<(NROWS + NCENT) / 8, 256>>>(x, cent);
    mma_score_kernel<<<dim3(NCENT / BN, NROWS / BM), 256, DSM_BYTES>>>();
    rescore_gather_kernel<<<NROWS / 8, 256>>>(x, cent, table, bias, out);
}

// round 14
// speedup vs baseline: 1.7760x; 1.0556x over previous
#include <cuda_runtime.h>
#include <cuda_bf16.h>
#include <cstdint>

#define NROWS 16384
#define DIM   1024
#define NCENT 1024
#define MARGIN 0.35f

#define BM 128
#define BN 128
#define BK 32
#define PAD_K 40   // bf16 elems per smem row (80B stride -> conflict-free ldmatrix)
#define NITER (DIM / BK)
#define NGRP  (NCENT / 64)   // 16 col-groups of 64 per row
#define MAXCAND 64

// ---- scratch (device globals only; no runtime allocation allowed) ----
__device__ float              g_xsq[NROWS];
__device__ float              g_csq[NCENT];
__device__ float              g_tmin[(size_t)NROWS * NGRP];   // 1 MB
__device__ unsigned long long g_mask[(size_t)NROWS * NGRP];   // 2 MB
__device__ __nv_bfloat16      g_xb[(size_t)NROWS * DIM];      // 32 MB
__device__ __nv_bfloat16      g_cb[(size_t)NCENT * DIM];      //  2 MB

// ---------------------------------------------------------------------------
// Prep, warp-per-row: 8 rows per 256-thread block, no block barriers.
// Rows [0,NROWS) = x, [NROWS,NROWS+NCENT) = centroids.
// Exact fp32 sum-of-squares (warp butterfly) + bf16 conversion.
// ---------------------------------------------------------------------------
__global__ __launch_bounds__(256) void prep_kernel(
    const float* __restrict__ x, const float* __restrict__ c)
{
    const int w = threadIdx.x >> 5, lane = threadIdx.x & 31;
    const int row = blockIdx.x * 8 + w;
    const bool isX = (row < NROWS);
    const int r = isX ? row : (row - NROWS);
    const float4* src = (const float4*)((isX ? x : c) + (size_t)r * DIM);
    __nv_bfloat162* dst = (__nv_bfloat162*)((isX ? g_xb : g_cb) + (size_t)r * DIM);

    float acc = 0.f;
    #pragma unroll
    for (int j = 0; j < 8; j++) {
        const int e = j * 32 + lane;          // float4 index within row
        const float4 v = src[e];
        __nv_bfloat162 b01, b23;
        b01.x = __float2bfloat16(v.x); b01.y = __float2bfloat16(v.y);
        b23.x = __float2bfloat16(v.z); b23.y = __float2bfloat16(v.w);
        dst[e * 2 + 0] = b01;
        dst[e * 2 + 1] = b23;
        acc = fmaf(v.x, v.x, acc);
        acc = fmaf(v.y, v.y, acc);
        acc = fmaf(v.z, v.z, acc);
        acc = fmaf(v.w, v.w, acc);
    }
    #pragma unroll
    for (int o = 16; o > 0; o >>= 1)
        acc += __shfl_xor_sync(0xffffffffu, acc, o);

    if (lane == 0) {
        if (isX) g_xsq[r] = acc;
        else     g_csq[r] = acc;
    }
}

// ---------------------------------------------------------------------------
// Stage 1: bf16 HMMA GEMM (measured-best mainloop), 128x128x32 tiles.
// Epilogue: fp32 scores s = -2dot+csq -> per-64col-group (min, margin-mask).
// No score matrix is materialized.
// ---------------------------------------------------------------------------
__device__ __forceinline__ void cp16(uint32_t dst, const void* src) {
    asm volatile("cp.async.cg.shared.global [%0], [%1], 16;\n" :: "r"(dst), "l"(src));
}
__device__ __forceinline__ void ldsm4(uint32_t* r, uint32_t addr) {
    asm volatile("ldmatrix.sync.aligned.m8n8.x4.shared.b16 {%0,%1,%2,%3}, [%4];"
                 : "=r"(r[0]), "=r"(r[1]), "=r"(r[2]), "=r"(r[3]) : "r"(addr));
}
__device__ __forceinline__ void mma16816(float* c, const uint32_t* a, uint32_t b0, uint32_t b1) {
    asm volatile("mma.sync.aligned.m16n8k16.row.col.f32.bf16.bf16.f32 "
                 "{%0,%1,%2,%3}, {%4,%5,%6,%7}, {%8,%9}, {%0,%1,%2,%3};"
                 : "+f"(c[0]), "+f"(c[1]), "+f"(c[2]), "+f"(c[3])
                 : "r"(a[0]), "r"(a[1]), "r"(a[2]), "r"(a[3]), "r"(b0), "r"(b1));
}

#define TILE_HALF (BM * PAD_K)                 // bf16 elems per tile buffer
#define DSM_BYTES (4 * TILE_HALF * 2)          // 40960 B (2 bufs x (A+B))

__global__ __launch_bounds__(256, 2) void mma_score_kernel() {
    extern __shared__ __align__(128) char dsm[];
    __shared__ float s_csq[BN];

    const int tid  = threadIdx.x;
    const int warp = tid >> 5, lane = tid & 31;
    const int wm = warp >> 1, wn = warp & 1;
    const int m0 = blockIdx.y * BM;
    const int n0 = blockIdx.x * BN;

    float acc[2][8][4];
    #pragma unroll
    for (int i = 0; i < 2; i++)
        #pragma unroll
        for (int j = 0; j < 8; j++)
            #pragma unroll
            for (int k = 0; k < 4; k++) acc[i][j][k] = 0.f;

    const uint32_t sbase = (uint32_t)__cvta_generic_to_shared(dsm);
    uint32_t sA[2], sB[2];
    sA[0] = sbase;
    sA[1] = sbase + TILE_HALF * 2;
    sB[0] = sbase + 2 * TILE_HALF * 2;
    sB[1] = sbase + 3 * TILE_HALF * 2;

    if (tid < BN / 2)
        *(float2*)&s_csq[tid * 2] = *(const float2*)&g_csq[n0 + tid * 2];

    // tile loaders: thread -> row tid>>1, 32B half (tid&1)
    const int lr = tid >> 1;
    const int lc = (tid & 1) * 16;
    const uint32_t dOff = (uint32_t)(lr * PAD_K + lc) * 2;

    auto load_tile = [&](int buf, int k0) {
        const __nv_bfloat16* srcA = g_xb + (size_t)(m0 + lr) * DIM + k0 + lc;
        cp16(sA[buf] + dOff,      srcA);
        cp16(sA[buf] + dOff + 16, srcA + 8);
        const __nv_bfloat16* srcB = g_cb + (size_t)(n0 + lr) * DIM + k0 + lc;
        cp16(sB[buf] + dOff,      srcB);
        cp16(sB[buf] + dOff + 16, srcB + 8);
    };

    load_tile(0, 0);
    asm volatile("cp.async.commit_group;");
    asm volatile("cp.async.wait_group 0;");
    __syncthreads();

    // ldmatrix lane geometry
    const int a_row = (lane & 7) + ((lane >> 3) & 1) * 8;
    const int a_kof = (lane >> 4) * 8;
    const int b_row = (lane & 7) + (lane >> 4) * 8;
    const int b_kof = ((lane >> 3) & 1) * 8;

    #pragma unroll 1
    for (int kt = 0; kt < NITER; kt++) {
        const int buf = kt & 1;
        if (kt + 1 < NITER) {
            load_tile(buf ^ 1, (kt + 1) * BK);
            asm volatile("cp.async.commit_group;");
        }

        #pragma unroll
        for (int ks = 0; ks < BK; ks += 16) {
            uint32_t af[2][4];
            #pragma unroll
            for (int mi = 0; mi < 2; mi++) {
                uint32_t addr = sA[buf] +
                    (uint32_t)((wm * 32 + mi * 16 + a_row) * PAD_K + ks + a_kof) * 2;
                ldsm4(af[mi], addr);
            }
            #pragma unroll
            for (int nt = 0; nt < 4; nt++) {
                uint32_t bf[4];
                uint32_t addr = sB[buf] +
                    (uint32_t)((wn * 64 + nt * 16 + b_row) * PAD_K + ks + b_kof) * 2;
                ldsm4(bf, addr);
                #pragma unroll
                for (int mi = 0; mi < 2; mi++) {
                    mma16816(acc[mi][2 * nt + 0], af[mi], bf[0], bf[1]);
                    mma16816(acc[mi][2 * nt + 1], af[mi], bf[2], bf[3]);
                }
            }
        }

        asm volatile("cp.async.wait_group 0;");
        __syncthreads();
    }

    // ---- epilogue: per (row, 64-col group): fp32 min + margin bitmask ----
    // Warp wn covers group grp = blockIdx.x*2 + wn; 4 lanes per row.
    const int grp = blockIdx.x * 2 + wn;
    #pragma unroll
    for (int mi = 0; mi < 2; mi++) {
        #pragma unroll
        for (int h = 0; h < 2; h++) {
            const int rl = wm * 32 + mi * 16 + h * 8 + (lane >> 2);  // local row
            float sc[16];
            float lmin = 3.4e38f;
            #pragma unroll
            for (int ni = 0; ni < 8; ni++) {
                const int cl = wn * 64 + ni * 8 + (lane & 3) * 2;    // local col
                const float s0 = fmaf(-2.f, acc[mi][ni][h * 2 + 0], s_csq[cl + 0]);
                const float s1 = fmaf(-2.f, acc[mi][ni][h * 2 + 1], s_csq[cl + 1]);
                sc[2 * ni + 0] = s0;
                sc[2 * ni + 1] = s1;
                lmin = fminf(lmin, fminf(s0, s1));
            }
            // group min across the 4 lanes of this row
            lmin = fminf(lmin, __shfl_xor_sync(0xffffffffu, lmin, 1));
            lmin = fminf(lmin, __shfl_xor_sync(0xffffffffu, lmin, 2));
            // margin mask (fp32 scores, local threshold — superset-safe)
            const float thr = lmin + MARGIN;
            unsigned long long m = 0ull;
            #pragma unroll
            for (int ni = 0; ni < 8; ni++) {
                const int bp = ni * 8 + (lane & 3) * 2;  // bit pos within group
                if (sc[2 * ni + 0] <= thr) m |= 1ull << bp;
                if (sc[2 * ni + 1] <= thr) m |= 1ull << (bp + 1);
            }
            m |= __shfl_xor_sync(0xffffffffu, m, 1);
            m |= __shfl_xor_sync(0xffffffffu, m, 2);
            if ((lane & 3) == 0) {
                const size_t o = (size_t)(m0 + rl) * NGRP + grp;
                g_tmin[o] = lmin;
                g_mask[o] = m;
            }
        }
    }
}

// ---------------------------------------------------------------------------
// Stage 2 (fused): warp-per-row candidate resolve + gather. 8 rows per block,
// no block barriers. gmin from 16 group-mins; decode masks of qualifying
// groups; cnt==1 fast path; exact fp32 rescore otherwise (reference-faithful
// fmaf(-2,dot,xsq)+csq, lowest-index tie-break). Gather fused.
// ---------------------------------------------------------------------------
__global__ __launch_bounds__(256) void rescore_gather_kernel(
    const float* __restrict__ x, const float* __restrict__ cent,
    const float* __restrict__ table, const float* __restrict__ bias,
    float* __restrict__ out)
{
    __shared__ int s_cand[8][MAXCAND];
    __shared__ int s_cnt[8];

    const int w = threadIdx.x >> 5, lane = threadIdx.x & 31;
    const int r = blockIdx.x * 8 + w;

    if (lane == 0) s_cnt[w] = 0;
    __syncwarp();

    const float tmin = (lane < NGRP) ? g_tmin[(size_t)r * NGRP + lane] : 3.4e38f;
    float gmin = tmin;
    #pragma unroll
    for (int o = 16; o > 0; o >>= 1)
        gmin = fminf(gmin, __shfl_xor_sync(0xffffffffu, gmin, o));
    const float thr = gmin + MARGIN;

    if (lane < NGRP && tmin <= thr) {
        unsigned long long m = g_mask[(size_t)r * NGRP + lane];
        while (m) {
            const int b = __ffsll((long long)m) - 1;
            m &= m - 1;
            const int p = atomicAdd(&s_cnt[w], 1);
            if (p < MAXCAND) s_cand[w][p] = lane * 64 + b;
        }
    }
    __syncwarp();
    const int cnt = min(s_cnt[w], MAXCAND);

    int bidx;
    if (cnt == 1) {               // unique candidate within margin: exact winner
        bidx = s_cand[w][0];
    } else {
        // x row strided into regs: xv[j] = x[r][j*32 + lane] (coalesced per j)
        const float* xr = x + (size_t)r * DIM;
        float xv[32];
        #pragma unroll
        for (int j = 0; j < 32; j++) xv[j] = xr[j * 32 + lane];
        const float xs = g_xsq[r];

        float best = 3.4e38f;
        bidx = NCENT;
        for (int ci = 0; ci < cnt; ci++) {
            const int c = s_cand[w][ci];
            const float* cr = cent + (size_t)c * DIM;
            float a = 0.f;
            #pragma unroll
            for (int j = 0; j < 32; j++)
                a = fmaf(xv[j], cr[j * 32 + lane], a);
            #pragma unroll
            for (int o = 16; o > 0; o >>= 1)
                a += __shfl_xor_sync(0xffffffffu, a, o);
            const float d = fmaf(-2.f, a, xs) + g_csq[c];
            if (d < best || (d == best && c < bidx)) { best = d; bidx = c; }
        }
    }

    // gather: out[r] = table[bidx] + bias (warp-coalesced float4 sweeps)
    const float4* src = (const float4*)(table + (size_t)bidx * DIM);
    const float4* bv  = (const float4*)bias;
    float4* dst = (float4*)(out + (size_t)r * DIM);
    #pragma unroll
    for (int j = 0; j < 8; j++) {
        const float4 a = src[j * 32 + lane];
        const float4 b = bv[j * 32 + lane];
        dst[j * 32 + lane] = make_float4(a.x + b.x, a.y + b.y, a.z + b.z, a.w + b.w);
    }
}

// ---------------------------------------------------------------------------
extern "C" void kernel_launch(void* const* d_in, const int* in_sizes, int n_in,
                              void* d_out, int out_size) {
    const float* x     = (const float*)d_in[0];  // [4,4096,1024]
    const float* cent  = (const float*)d_in[1];  // [1024,1024]
    const float* table = (const float*)d_in[2];  // [1024,1024]
    const float* bias  = (const float*)d_in[3];  // [1024]
    float* out = (float*)d_out;

    cudaFuncSetAttribute(mma_score_kernel,
                         cudaFuncAttributeMaxDynamicSharedMemorySize, DSM_BYTES);

    prep_kernel<<<(NROWS + NCENT) / 8, 256>>>(x, cent);
    mma_score_kernel<<<dim3(NCENT / BN, NROWS / BM), 256, DSM_BYTES>>>();
    rescore_gather_kernel<<<NROWS / 8, 256>>>(x, cent, table, bias, out);
}